// round 3
// baseline (speedup 1.0000x reference)
#include <cuda_runtime.h>
#include <math.h>

#define BATCH 4
#define SEQ   2048
#define FEATS 1024
#define NHEAD 16
#define HD    64
#define MROWS (BATCH*SEQ)

// ---------------- scratch (static device globals; no allocations) ----------
__device__ float g_Q[BATCH*NHEAD*SEQ*HD];   // [b,h,n,d]
__device__ float g_K[BATCH*NHEAD*SEQ*HD];
__device__ float g_V[BATCH*NHEAD*SEQ*HD];
__device__ float g_A[MROWS*FEATS];          // attention out, [b,n,h,d] == [m, f]

// ---------------------------------------------------------------------------
// GEMM: C[m, n] = sum_k A[m,k] * W[n,k] + bias[n]
// A: [MROWS, FEATS], W: [FEATS, FEATS] row-major. 128x128x8 tile, 256 thr,
// 8x8 per-thread microtile. qkv_layout=1 remaps output to [b,h,n,d].
// ---------------------------------------------------------------------------
__global__ __launch_bounds__(256) void gemm_bias_kernel(
    const float* __restrict__ A, const float* __restrict__ W,
    const float* __restrict__ bias, float* __restrict__ C, int qkv_layout)
{
    __shared__ float As[8][128];
    __shared__ float Bs[8][128];

    const int tid  = threadIdx.x;
    const int row0 = blockIdx.y * 128;
    const int col0 = blockIdx.x * 128;
    const int lrow = tid >> 1;            // 0..127
    const int lcol = (tid & 1) << 2;      // 0 or 4
    const float* Ap = A + (size_t)(row0 + lrow) * FEATS + lcol;
    const float* Wp = W + (size_t)(col0 + lrow) * FEATS + lcol;

    const int tx = tid & 15;              // 16 cols of threads
    const int ty = tid >> 4;              // 16 rows of threads

    float acc[8][8];
#pragma unroll
    for (int i = 0; i < 8; i++)
#pragma unroll
        for (int j = 0; j < 8; j++) acc[i][j] = 0.0f;

    for (int k0 = 0; k0 < FEATS; k0 += 8) {
        float4 av = *(const float4*)(Ap + k0);
        float4 wv = *(const float4*)(Wp + k0);
        __syncthreads();
        As[lcol+0][lrow] = av.x; As[lcol+1][lrow] = av.y;
        As[lcol+2][lrow] = av.z; As[lcol+3][lrow] = av.w;
        Bs[lcol+0][lrow] = wv.x; Bs[lcol+1][lrow] = wv.y;
        Bs[lcol+2][lrow] = wv.z; Bs[lcol+3][lrow] = wv.w;
        __syncthreads();
#pragma unroll
        for (int kk = 0; kk < 8; kk++) {
            float a[8], bb[8];
            *(float4*)(a)     = *(const float4*)&As[kk][ty*8];
            *(float4*)(a + 4) = *(const float4*)&As[kk][ty*8 + 4];
            *(float4*)(bb)    = *(const float4*)&Bs[kk][tx*8];
            *(float4*)(bb + 4)= *(const float4*)&Bs[kk][tx*8 + 4];
#pragma unroll
            for (int i = 0; i < 8; i++)
#pragma unroll
                for (int j = 0; j < 8; j++)
                    acc[i][j] = fmaf(a[i], bb[j], acc[i][j]);
        }
    }

    // epilogue
#pragma unroll
    for (int i = 0; i < 8; i++) {
        const int m    = row0 + ty*8 + i;
        const int b_   = m >> 11;          // m / SEQ
        const int nseq = m & (SEQ - 1);
#pragma unroll
        for (int j = 0; j < 8; j++) {
            const int c = col0 + tx*8 + j;
            const float v = acc[i][j] + bias[c];
            if (qkv_layout) {
                const int h = c >> 6, d = c & 63;
                C[(((size_t)(b_*NHEAD + h))*SEQ + nseq)*HD + d] = v;
            } else {
                C[(size_t)m * FEATS + c] = v;
            }
        }
    }
}

// ---------------------------------------------------------------------------
// Flash attention: per (b,h), 64-query tiles, 64-key tiles, hd=64.
// Q pre-scaled by 1/32. Online softmax; 16-lane butterfly reductions.
// Static smem, 48KB exactly: Qs + Ks + Vs; P-tile aliases Ks (K dead after S).
// Output written as [b, n, h, d]  (ready for the O projection GEMM).
// ---------------------------------------------------------------------------
__global__ __launch_bounds__(256) void attn_kernel(
    const float* __restrict__ Qg, const float* __restrict__ Kg,
    const float* __restrict__ Vg, float* __restrict__ Og)
{
    __shared__ float Qs[64*64];   // [query][d]
    __shared__ float Ks[64*64];   // [d][key] transposed; later reused as P [query][key]
    __shared__ float Vs[64*64];   // [key][d]
    float* Ps = Ks;               // alias: K tile dead once S is computed

    const int tid = threadIdx.x;
    const int tx  = tid & 15;      // key / hd tile position (4 wide)
    const int ty  = tid >> 4;      // query tile position (4 tall)
    const int row = ty * 4;

    const int bh = blockIdx.y;
    const int q0 = blockIdx.x * 64;
    const float* Qb = Qg + ((size_t)bh * SEQ + q0) * HD;
    const float* Kb = Kg + (size_t)bh * SEQ * HD;
    const float* Vb = Vg + (size_t)bh * SEQ * HD;
    const float scale = 1.0f / 32.0f;   // 1/sqrt(FEATS)

    // Load + pre-scale Q tile
    for (int t = tid; t < 64*16; t += 256) {
        const int r = t >> 4, c4 = (t & 15) << 2;
        float4 v = *(const float4*)(Qb + r*HD + c4);
        v.x *= scale; v.y *= scale; v.z *= scale; v.w *= scale;
        *(float4*)&Qs[r*64 + c4] = v;
    }

    float m_i[4], l_i[4], o[4][4];
#pragma unroll
    for (int i = 0; i < 4; i++) {
        m_i[i] = -1e30f; l_i[i] = 0.0f;
#pragma unroll
        for (int j = 0; j < 4; j++) o[i][j] = 0.0f;
    }

    for (int kt = 0; kt < SEQ/64; kt++) {
        __syncthreads();   // prior-iter PV readers done with Vs/Ps(=Ks)
        const float* Kt = Kb + (size_t)kt * 64 * HD;
        const float* Vt = Vb + (size_t)kt * 64 * HD;
        for (int t = tid; t < 64*16; t += 256) {
            const int r = t >> 4, c4 = (t & 15) << 2;
            float4 kv = *(const float4*)(Kt + r*HD + c4);
            Ks[(c4+0)*64 + r] = kv.x;
            Ks[(c4+1)*64 + r] = kv.y;
            Ks[(c4+2)*64 + r] = kv.z;
            Ks[(c4+3)*64 + r] = kv.w;
            *(float4*)&Vs[r*64 + c4] = *(const float4*)(Vt + r*HD + c4);
        }
        __syncthreads();

        // S = Q K^T  (4x4 per thread), k in steps of 4, all .128 LDS
        float s[4][4];
#pragma unroll
        for (int i = 0; i < 4; i++)
#pragma unroll
            for (int j = 0; j < 4; j++) s[i][j] = 0.0f;

        for (int k4 = 0; k4 < HD; k4 += 4) {
            float qa[4][4], kb[4][4];
#pragma unroll
            for (int i = 0; i < 4; i++)
                *(float4*)qa[i] = *(const float4*)&Qs[(row+i)*64 + k4];
#pragma unroll
            for (int u = 0; u < 4; u++)
                *(float4*)kb[u] = *(const float4*)&Ks[(k4+u)*64 + tx*4];
#pragma unroll
            for (int u = 0; u < 4; u++)
#pragma unroll
                for (int i = 0; i < 4; i++)
#pragma unroll
                    for (int j = 0; j < 4; j++)
                        s[i][j] = fmaf(qa[i][u], kb[u][j], s[i][j]);
        }
        __syncthreads();   // everyone done reading Ks before P overwrites it

        // online softmax
#pragma unroll
        for (int i = 0; i < 4; i++) {
            float mt = fmaxf(fmaxf(s[i][0], s[i][1]), fmaxf(s[i][2], s[i][3]));
            mt = fmaxf(mt, __shfl_xor_sync(0xffffffffu, mt, 8));
            mt = fmaxf(mt, __shfl_xor_sync(0xffffffffu, mt, 4));
            mt = fmaxf(mt, __shfl_xor_sync(0xffffffffu, mt, 2));
            mt = fmaxf(mt, __shfl_xor_sync(0xffffffffu, mt, 1));
            const float mnew = fmaxf(m_i[i], mt);
            float p0 = __expf(s[i][0] - mnew);
            float p1 = __expf(s[i][1] - mnew);
            float p2 = __expf(s[i][2] - mnew);
            float p3 = __expf(s[i][3] - mnew);
            float rs = p0 + p1 + p2 + p3;
            rs += __shfl_xor_sync(0xffffffffu, rs, 8);
            rs += __shfl_xor_sync(0xffffffffu, rs, 4);
            rs += __shfl_xor_sync(0xffffffffu, rs, 2);
            rs += __shfl_xor_sync(0xffffffffu, rs, 1);
            const float alpha = __expf(m_i[i] - mnew);
            l_i[i] = l_i[i] * alpha + rs;
            m_i[i] = mnew;
#pragma unroll
            for (int j = 0; j < 4; j++) o[i][j] *= alpha;
            float4 pv = make_float4(p0, p1, p2, p3);
            *(float4*)&Ps[(row+i)*64 + tx*4] = pv;
        }
        __syncthreads();

        // O += P V  (kk in steps of 4)
        for (int kk4 = 0; kk4 < 64; kk4 += 4) {
            float pa[4][4], vb[4][4];
#pragma unroll
            for (int i = 0; i < 4; i++)
                *(float4*)pa[i] = *(const float4*)&Ps[(row+i)*64 + kk4];
#pragma unroll
            for (int u = 0; u < 4; u++)
                *(float4*)vb[u] = *(const float4*)&Vs[(kk4+u)*64 + tx*4];
#pragma unroll
            for (int u = 0; u < 4; u++)
#pragma unroll
                for (int i = 0; i < 4; i++)
#pragma unroll
                    for (int j = 0; j < 4; j++)
                        o[i][j] = fmaf(pa[i][u], vb[u][j], o[i][j]);
        }
    }

    // epilogue -> [b, n, h, d]
    const int b_ = bh >> 4, h = bh & 15;
#pragma unroll
    for (int i = 0; i < 4; i++) {
        const int n = q0 + row + i;
        const float inv = 1.0f / l_i[i];
        float4 ov = make_float4(o[i][0]*inv, o[i][1]*inv, o[i][2]*inv, o[i][3]*inv);
        *(float4*)&Og[(((size_t)b_*SEQ + n)*NHEAD + h)*HD + tx*4] = ov;
    }
}

// ---------------------------------------------------------------------------
extern "C" void kernel_launch(void* const* d_in, const int* in_sizes, int n_in,
                              void* d_out, int out_size)
{
    const float* x  = (const float*)d_in[0];
    const float* Wq = (const float*)d_in[1];
    const float* bq = (const float*)d_in[2];
    const float* Wk = (const float*)d_in[3];
    const float* bk = (const float*)d_in[4];
    const float* Wv = (const float*)d_in[5];
    const float* bv = (const float*)d_in[6];
    const float* Wo = (const float*)d_in[7];
    const float* bo = (const float*)d_in[8];
    float* out = (float*)d_out;

    float *Qb, *Kb, *Vb, *Ab;
    cudaGetSymbolAddress((void**)&Qb, g_Q);
    cudaGetSymbolAddress((void**)&Kb, g_K);
    cudaGetSymbolAddress((void**)&Vb, g_V);
    cudaGetSymbolAddress((void**)&Ab, g_A);

    dim3 ggrid(FEATS/128, MROWS/128);   // (8, 64)
    gemm_bias_kernel<<<ggrid, 256>>>(x, Wq, bq, Qb, 1);
    gemm_bias_kernel<<<ggrid, 256>>>(x, Wk, bk, Kb, 1);
    gemm_bias_kernel<<<ggrid, 256>>>(x, Wv, bv, Vb, 1);

    dim3 agrid(SEQ/64, BATCH*NHEAD);    // (32, 64)
    attn_kernel<<<agrid, 256>>>(Qb, Kb, Vb, Ab);

    gemm_bias_kernel<<<ggrid, 256>>>(Ab, Wo, bo, out, 0);
}

// round 12
// speedup vs baseline: 1.3501x; 1.3501x over previous
#include <cuda_runtime.h>
#include <cstdint>
#include <math.h>

#define BATCH 4
#define SEQ   2048
#define FEATS 1024
#define NHEAD 16
#define HD    64
#define MROWS (BATCH*SEQ)

// ---------------- scratch (static device globals; no allocations) ----------
__device__ float g_Q[BATCH*NHEAD*SEQ*HD];   // [b,h,n,d]
__device__ float g_K[BATCH*NHEAD*SEQ*HD];
__device__ float g_V[BATCH*NHEAD*SEQ*HD];
__device__ float g_A[MROWS*FEATS];          // attention out, [b,n,h,d] == [m, f]

// ======================= portable PTX helpers (no 'a'-gated features) ======
__device__ __forceinline__ uint32_t smem_u32(const void* p) {
    uint32_t a;
    asm("{ .reg .u64 t; cvta.to.shared.u64 t, %1; cvt.u32.u64 %0, t; }"
        : "=r"(a) : "l"(p));
    return a;
}
#define CP_ASYNC16(saddr, gptr) \
    asm volatile("cp.async.cg.shared.global [%0], [%1], 16;" \
        :: "r"((uint32_t)(saddr)), "l"(gptr))
#define CP_COMMIT() asm volatile("cp.async.commit_group;" ::: "memory")
#define CP_WAIT(n)  asm volatile("cp.async.wait_group %0;" :: "n"(n) : "memory")

__device__ __forceinline__ uint32_t f2tf32(float f) {
    uint32_t r;
    asm("cvt.rna.tf32.f32 %0, %1;" : "=r"(r) : "f"(f));
    return r;
}
__device__ __forceinline__ void mma_tf32(float c[4], uint32_t a0, uint32_t a1,
                                         uint32_t a2, uint32_t a3,
                                         uint32_t b0, uint32_t b1) {
    asm volatile(
        "mma.sync.aligned.m16n8k8.row.col.f32.tf32.tf32.f32 "
        "{%0,%1,%2,%3}, {%4,%5,%6,%7}, {%8,%9}, {%0,%1,%2,%3};"
        : "+f"(c[0]), "+f"(c[1]), "+f"(c[2]), "+f"(c[3])
        : "r"(a0), "r"(a1), "r"(a2), "r"(a3), "r"(b0), "r"(b1));
}

// ---------------------------------------------------------------------------
// tf32 mma.sync GEMM:  C[m, col] = sum_k X[m,k] * W[col,k] + bias[col]
// CTA 128x128, 8 warps (2m x 4n), warp tile 64x32. K chunk 32, cp.async
// double buffered. Smem row stride 36 floats (conflict-free frag loads).
// qkv_layout=1 remaps output cols to [b,h,n,d].
// ---------------------------------------------------------------------------
#define KC   32
#define SS   36                   // smem row stride in floats
#define BUFE (128*SS)             // floats per tile buffer
#define GSM_BYTES (4*BUFE*4)      // As0,As1,Bs0,Bs1 = 73728 B

__device__ __forceinline__ void stage_chunk(
    const float* __restrict__ X, const float* __restrict__ W,
    uint32_t sA, uint32_t sB, int mrow0, int ncol0, int k0, int tid)
{
    const int r0 = tid >> 2;            // 0..63
    const int f4 = tid & 3;             // 0..3
#pragma unroll
    for (int rr = 0; rr < 2; rr++) {
        const int r = r0 + rr*64;
#pragma unroll
        for (int ff = 0; ff < 2; ff++) {
            const int c = (f4 + ff*4) * 4;   // float col within chunk
            CP_ASYNC16(sA + (uint32_t)(r*SS + c)*4,
                       X + (size_t)(mrow0 + r)*FEATS + k0 + c);
            CP_ASYNC16(sB + (uint32_t)(r*SS + c)*4,
                       W + (size_t)(ncol0 + r)*FEATS + k0 + c);
        }
    }
}

__global__ __launch_bounds__(256) void gemm_mma_kernel(
    const float* __restrict__ X, const float* __restrict__ W,
    const float* __restrict__ bias, float* __restrict__ C, int qkv_layout)
{
    extern __shared__ __align__(16) float smf[];
    const uint32_t smem_base = smem_u32(smf);

    const int tid  = threadIdx.x;
    const int wid  = tid >> 5, lane = tid & 31;
    const int gid  = lane >> 2, tg = lane & 3;
    const int wm0  = (wid & 1) * 64;      // warp m offset in tile
    const int wn0  = (wid >> 1) * 32;     // warp n offset in tile
    const int mrow0 = blockIdx.x * 128;
    const int ncol0 = blockIdx.y * 128;

    const uint32_t sA[2] = { smem_base,              smem_base + BUFE*4 };
    const uint32_t sB[2] = { smem_base + 2*BUFE*4,   smem_base + 3*BUFE*4 };
    const float*   fA[2] = { smf,          smf + BUFE };
    const float*   fB[2] = { smf + 2*BUFE, smf + 3*BUFE };

    float acc[4][4][4];                   // [mf][nf][frag]
#pragma unroll
    for (int i = 0; i < 4; i++)
#pragma unroll
        for (int j = 0; j < 4; j++)
#pragma unroll
            for (int q = 0; q < 4; q++) acc[i][j][q] = 0.0f;

    stage_chunk(X, W, sA[0], sB[0], mrow0, ncol0, 0, tid);
    CP_COMMIT();

    for (int ck = 0; ck < FEATS/KC; ck++) {
        if (ck < FEATS/KC - 1) {
            stage_chunk(X, W, sA[(ck+1)&1], sB[(ck+1)&1],
                        mrow0, ncol0, (ck+1)*KC, tid);
            CP_COMMIT();
            CP_WAIT(1);
        } else {
            CP_WAIT(0);
        }
        __syncthreads();

        const float* As = fA[ck & 1];
        const float* Bs = fB[ck & 1];
#pragma unroll
        for (int kk = 0; kk < 4; kk++) {
            const int k = kk*8 + tg;
            uint32_t a[4][4];
#pragma unroll
            for (int mf = 0; mf < 4; mf++) {
                const int row = wm0 + mf*16 + gid;
                a[mf][0] = f2tf32(As[(row  )*SS + k    ]);
                a[mf][1] = f2tf32(As[(row+8)*SS + k    ]);
                a[mf][2] = f2tf32(As[(row  )*SS + k + 4]);
                a[mf][3] = f2tf32(As[(row+8)*SS + k + 4]);
            }
            uint32_t b[4][2];
#pragma unroll
            for (int nf = 0; nf < 4; nf++) {
                const int n = wn0 + nf*8 + gid;
                b[nf][0] = f2tf32(Bs[n*SS + k    ]);
                b[nf][1] = f2tf32(Bs[n*SS + k + 4]);
            }
#pragma unroll
            for (int mf = 0; mf < 4; mf++)
#pragma unroll
                for (int nf = 0; nf < 4; nf++)
                    mma_tf32(acc[mf][nf], a[mf][0], a[mf][1], a[mf][2], a[mf][3],
                             b[nf][0], b[nf][1]);
        }
        __syncthreads();
    }

    // epilogue: c0,c1 -> (row, col..col+1); c2,c3 -> (row+8, ...)
#pragma unroll
    for (int nf = 0; nf < 4; nf++) {
        const int col = ncol0 + wn0 + nf*8 + 2*tg;
        const float bv0 = bias[col], bv1 = bias[col + 1];
        const int h = col >> 6, d = col & 63;
#pragma unroll
        for (int mf = 0; mf < 4; mf++) {
#pragma unroll
            for (int half = 0; half < 2; half++) {
                const int m = mrow0 + wm0 + mf*16 + gid + half*8;
                const float v0 = acc[mf][nf][half*2 + 0] + bv0;
                const float v1 = acc[mf][nf][half*2 + 1] + bv1;
                if (qkv_layout) {
                    const int b_ = m >> 11, ns = m & (SEQ - 1);
                    *(float2*)&C[(((size_t)(b_*NHEAD + h))*SEQ + ns)*HD + d] =
                        make_float2(v0, v1);
                } else {
                    *(float2*)&C[(size_t)m*FEATS + col] = make_float2(v0, v1);
                }
            }
        }
    }
}

// ---------------------------------------------------------------------------
// Flash attention (unchanged from R3 pass): fp32, 64x64 tiles, static 48KB.
// ---------------------------------------------------------------------------
__global__ __launch_bounds__(256) void attn_kernel(
    const float* __restrict__ Qg, const float* __restrict__ Kg,
    const float* __restrict__ Vg, float* __restrict__ Og)
{
    __shared__ float Qs[64*64];
    __shared__ float Ks[64*64];
    __shared__ float Vs[64*64];
    float* Ps = Ks;

    const int tid = threadIdx.x;
    const int tx  = tid & 15;
    const int ty  = tid >> 4;
    const int row = ty * 4;

    const int bh = blockIdx.y;
    const int q0 = blockIdx.x * 64;
    const float* Qb = Qg + ((size_t)bh * SEQ + q0) * HD;
    const float* Kb = Kg + (size_t)bh * SEQ * HD;
    const float* Vb = Vg + (size_t)bh * SEQ * HD;
    const float scale = 1.0f / 32.0f;

    for (int t = tid; t < 64*16; t += 256) {
        const int r = t >> 4, c4 = (t & 15) << 2;
        float4 v = *(const float4*)(Qb + r*HD + c4);
        v.x *= scale; v.y *= scale; v.z *= scale; v.w *= scale;
        *(float4*)&Qs[r*64 + c4] = v;
    }

    float m_i[4], l_i[4], o[4][4];
#pragma unroll
    for (int i = 0; i < 4; i++) {
        m_i[i] = -1e30f; l_i[i] = 0.0f;
#pragma unroll
        for (int j = 0; j < 4; j++) o[i][j] = 0.0f;
    }

    for (int kt = 0; kt < SEQ/64; kt++) {
        __syncthreads();
        const float* Kt = Kb + (size_t)kt * 64 * HD;
        const float* Vt = Vb + (size_t)kt * 64 * HD;
        for (int t = tid; t < 64*16; t += 256) {
            const int r = t >> 4, c4 = (t & 15) << 2;
            float4 kv = *(const float4*)(Kt + r*HD + c4);
            Ks[(c4+0)*64 + r] = kv.x;
            Ks[(c4+1)*64 + r] = kv.y;
            Ks[(c4+2)*64 + r] = kv.z;
            Ks[(c4+3)*64 + r] = kv.w;
            *(float4*)&Vs[r*64 + c4] = *(const float4*)(Vt + r*HD + c4);
        }
        __syncthreads();

        float s[4][4];
#pragma unroll
        for (int i = 0; i < 4; i++)
#pragma unroll
            for (int j = 0; j < 4; j++) s[i][j] = 0.0f;

        for (int k4 = 0; k4 < HD; k4 += 4) {
            float qa[4][4], kb[4][4];
#pragma unroll
            for (int i = 0; i < 4; i++)
                *(float4*)qa[i] = *(const float4*)&Qs[(row+i)*64 + k4];
#pragma unroll
            for (int u = 0; u < 4; u++)
                *(float4*)kb[u] = *(const float4*)&Ks[(k4+u)*64 + tx*4];
#pragma unroll
            for (int u = 0; u < 4; u++)
#pragma unroll
                for (int i = 0; i < 4; i++)
#pragma unroll
                    for (int j = 0; j < 4; j++)
                        s[i][j] = fmaf(qa[i][u], kb[u][j], s[i][j]);
        }
        __syncthreads();

#pragma unroll
        for (int i = 0; i < 4; i++) {
            float mt = fmaxf(fmaxf(s[i][0], s[i][1]), fmaxf(s[i][2], s[i][3]));
            mt = fmaxf(mt, __shfl_xor_sync(0xffffffffu, mt, 8));
            mt = fmaxf(mt, __shfl_xor_sync(0xffffffffu, mt, 4));
            mt = fmaxf(mt, __shfl_xor_sync(0xffffffffu, mt, 2));
            mt = fmaxf(mt, __shfl_xor_sync(0xffffffffu, mt, 1));
            const float mnew = fmaxf(m_i[i], mt);
            float p0 = __expf(s[i][0] - mnew);
            float p1 = __expf(s[i][1] - mnew);
            float p2 = __expf(s[i][2] - mnew);
            float p3 = __expf(s[i][3] - mnew);
            float rs = p0 + p1 + p2 + p3;
            rs += __shfl_xor_sync(0xffffffffu, rs, 8);
            rs += __shfl_xor_sync(0xffffffffu, rs, 4);
            rs += __shfl_xor_sync(0xffffffffu, rs, 2);
            rs += __shfl_xor_sync(0xffffffffu, rs, 1);
            const float alpha = __expf(m_i[i] - mnew);
            l_i[i] = l_i[i] * alpha + rs;
            m_i[i] = mnew;
#pragma unroll
            for (int j = 0; j < 4; j++) o[i][j] *= alpha;
            float4 pv = make_float4(p0, p1, p2, p3);
            *(float4*)&Ps[(row+i)*64 + tx*4] = pv;
        }
        __syncthreads();

        for (int kk4 = 0; kk4 < 64; kk4 += 4) {
            float pa[4][4], vb[4][4];
#pragma unroll
            for (int i = 0; i < 4; i++)
                *(float4*)pa[i] = *(const float4*)&Ps[(row+i)*64 + kk4];
#pragma unroll
            for (int u = 0; u < 4; u++)
                *(float4*)vb[u] = *(const float4*)&Vs[(kk4+u)*64 + tx*4];
#pragma unroll
            for (int u = 0; u < 4; u++)
#pragma unroll
                for (int i = 0; i < 4; i++)
#pragma unroll
                    for (int j = 0; j < 4; j++)
                        o[i][j] = fmaf(pa[i][u], vb[u][j], o[i][j]);
        }
    }

    const int b_ = bh >> 4, h = bh & 15;
#pragma unroll
    for (int i = 0; i < 4; i++) {
        const int n = q0 + row + i;
        const float inv = 1.0f / l_i[i];
        float4 ov = make_float4(o[i][0]*inv, o[i][1]*inv, o[i][2]*inv, o[i][3]*inv);
        *(float4*)&Og[(((size_t)b_*SEQ + n)*NHEAD + h)*HD + tx*4] = ov;
    }
}

// ---------------------------------------------------------------------------
extern "C" void kernel_launch(void* const* d_in, const int* in_sizes, int n_in,
                              void* d_out, int out_size)
{
    const float* x  = (const float*)d_in[0];
    const float* Wq = (const float*)d_in[1];
    const float* bq = (const float*)d_in[2];
    const float* Wk = (const float*)d_in[3];
    const float* bk = (const float*)d_in[4];
    const float* Wv = (const float*)d_in[5];
    const float* bv = (const float*)d_in[6];
    const float* Wo = (const float*)d_in[7];
    const float* bo = (const float*)d_in[8];
    float* out = (float*)d_out;

    float *Qb, *Kb, *Vb, *Ab;
    cudaGetSymbolAddress((void**)&Qb, g_Q);
    cudaGetSymbolAddress((void**)&Kb, g_K);
    cudaGetSymbolAddress((void**)&Vb, g_V);
    cudaGetSymbolAddress((void**)&Ab, g_A);

    cudaFuncSetAttribute(gemm_mma_kernel, cudaFuncAttributeMaxDynamicSharedMemorySize,
                         GSM_BYTES);

    dim3 ggrid(MROWS/128, FEATS/128);   // (64, 8)
    gemm_mma_kernel<<<ggrid, 256, GSM_BYTES>>>(x, Wq, bq, Qb, 1);
    gemm_mma_kernel<<<ggrid, 256, GSM_BYTES>>>(x, Wk, bk, Kb, 1);
    gemm_mma_kernel<<<ggrid, 256, GSM_BYTES>>>(x, Wv, bv, Vb, 1);

    dim3 agrid(SEQ/64, BATCH*NHEAD);    // (32, 64)
    attn_kernel<<<agrid, 256>>>(Qb, Kb, Vb, Ab);

    gemm_mma_kernel<<<ggrid, 256, GSM_BYTES>>>(Ab, Wo, bo, out, 0);
}

// round 13
// speedup vs baseline: 2.1651x; 1.6036x over previous
#include <cuda_runtime.h>
#include <cstdint>
#include <math.h>

#define BATCH 4
#define SEQ   2048
#define FEATS 1024
#define NHEAD 16
#define HD    64
#define MROWS (BATCH*SEQ)

// ---------------- scratch (static device globals; no allocations) ----------
__device__ float g_Q[BATCH*NHEAD*SEQ*HD];   // [b,h,n,d]
__device__ float g_K[BATCH*NHEAD*SEQ*HD];
__device__ float g_V[BATCH*NHEAD*SEQ*HD];
__device__ float g_A[MROWS*FEATS];          // attention out, [b,n,h,d] == [m, f]

// ======================= portable PTX helpers (no 'a'-gated features) ======
__device__ __forceinline__ uint32_t smem_u32(const void* p) {
    uint32_t a;
    asm("{ .reg .u64 t; cvta.to.shared.u64 t, %1; cvt.u32.u64 %0, t; }"
        : "=r"(a) : "l"(p));
    return a;
}
#define CP_ASYNC16(saddr, gptr) \
    asm volatile("cp.async.cg.shared.global [%0], [%1], 16;" \
        :: "r"((uint32_t)(saddr)), "l"(gptr))
#define CP_COMMIT() asm volatile("cp.async.commit_group;" ::: "memory")
#define CP_WAIT(n)  asm volatile("cp.async.wait_group %0;" :: "n"(n) : "memory")

__device__ __forceinline__ uint32_t f2tf32(float f) {
    uint32_t r;
    asm("cvt.rna.tf32.f32 %0, %1;" : "=r"(r) : "f"(f));
    return r;
}
__device__ __forceinline__ float tf32f(float f) {   // value-preserving tf32 round
    uint32_t r = f2tf32(f);
    return __uint_as_float(r);
}
__device__ __forceinline__ void mma_tf32(float c[4], uint32_t a0, uint32_t a1,
                                         uint32_t a2, uint32_t a3,
                                         uint32_t b0, uint32_t b1) {
    asm volatile(
        "mma.sync.aligned.m16n8k8.row.col.f32.tf32.tf32.f32 "
        "{%0,%1,%2,%3}, {%4,%5,%6,%7}, {%8,%9}, {%0,%1,%2,%3};"
        : "+f"(c[0]), "+f"(c[1]), "+f"(c[2]), "+f"(c[3])
        : "r"(a0), "r"(a1), "r"(a2), "r"(a3), "r"(b0), "r"(b1));
}

// ---------------------------------------------------------------------------
// tf32 mma.sync GEMM (unchanged from R12 pass):
// C[m, col] = sum_k X[m,k] * W[col,k] + bias[col]
// ---------------------------------------------------------------------------
#define KC   32
#define SS   36
#define BUFE (128*SS)
#define GSM_BYTES (4*BUFE*4)

__device__ __forceinline__ void stage_chunk(
    const float* __restrict__ X, const float* __restrict__ W,
    uint32_t sA, uint32_t sB, int mrow0, int ncol0, int k0, int tid)
{
    const int r0 = tid >> 2;
    const int f4 = tid & 3;
#pragma unroll
    for (int rr = 0; rr < 2; rr++) {
        const int r = r0 + rr*64;
#pragma unroll
        for (int ff = 0; ff < 2; ff++) {
            const int c = (f4 + ff*4) * 4;
            CP_ASYNC16(sA + (uint32_t)(r*SS + c)*4,
                       X + (size_t)(mrow0 + r)*FEATS + k0 + c);
            CP_ASYNC16(sB + (uint32_t)(r*SS + c)*4,
                       W + (size_t)(ncol0 + r)*FEATS + k0 + c);
        }
    }
}

__global__ __launch_bounds__(256) void gemm_mma_kernel(
    const float* __restrict__ X, const float* __restrict__ W,
    const float* __restrict__ bias, float* __restrict__ C, int qkv_layout)
{
    extern __shared__ __align__(16) float smf[];
    const uint32_t smem_base = smem_u32(smf);

    const int tid  = threadIdx.x;
    const int wid  = tid >> 5, lane = tid & 31;
    const int gid  = lane >> 2, tg = lane & 3;
    const int wm0  = (wid & 1) * 64;
    const int wn0  = (wid >> 1) * 32;
    const int mrow0 = blockIdx.x * 128;
    const int ncol0 = blockIdx.y * 128;

    const uint32_t sA[2] = { smem_base,              smem_base + BUFE*4 };
    const uint32_t sB[2] = { smem_base + 2*BUFE*4,   smem_base + 3*BUFE*4 };
    const float*   fA[2] = { smf,          smf + BUFE };
    const float*   fB[2] = { smf + 2*BUFE, smf + 3*BUFE };

    float acc[4][4][4];
#pragma unroll
    for (int i = 0; i < 4; i++)
#pragma unroll
        for (int j = 0; j < 4; j++)
#pragma unroll
            for (int q = 0; q < 4; q++) acc[i][j][q] = 0.0f;

    stage_chunk(X, W, sA[0], sB[0], mrow0, ncol0, 0, tid);
    CP_COMMIT();

    for (int ck = 0; ck < FEATS/KC; ck++) {
        if (ck < FEATS/KC - 1) {
            stage_chunk(X, W, sA[(ck+1)&1], sB[(ck+1)&1],
                        mrow0, ncol0, (ck+1)*KC, tid);
            CP_COMMIT();
            CP_WAIT(1);
        } else {
            CP_WAIT(0);
        }
        __syncthreads();

        const float* As = fA[ck & 1];
        const float* Bs = fB[ck & 1];
#pragma unroll
        for (int kk = 0; kk < 4; kk++) {
            const int k = kk*8 + tg;
            uint32_t a[4][4];
#pragma unroll
            for (int mf = 0; mf < 4; mf++) {
                const int row = wm0 + mf*16 + gid;
                a[mf][0] = f2tf32(As[(row  )*SS + k    ]);
                a[mf][1] = f2tf32(As[(row+8)*SS + k    ]);
                a[mf][2] = f2tf32(As[(row  )*SS + k + 4]);
                a[mf][3] = f2tf32(As[(row+8)*SS + k + 4]);
            }
            uint32_t b[4][2];
#pragma unroll
            for (int nf = 0; nf < 4; nf++) {
                const int n = wn0 + nf*8 + gid;
                b[nf][0] = f2tf32(Bs[n*SS + k    ]);
                b[nf][1] = f2tf32(Bs[n*SS + k + 4]);
            }
#pragma unroll
            for (int mf = 0; mf < 4; mf++)
#pragma unroll
                for (int nf = 0; nf < 4; nf++)
                    mma_tf32(acc[mf][nf], a[mf][0], a[mf][1], a[mf][2], a[mf][3],
                             b[nf][0], b[nf][1]);
        }
        __syncthreads();
    }

#pragma unroll
    for (int nf = 0; nf < 4; nf++) {
        const int col = ncol0 + wn0 + nf*8 + 2*tg;
        const float bv0 = bias[col], bv1 = bias[col + 1];
        const int h = col >> 6, d = col & 63;
#pragma unroll
        for (int mf = 0; mf < 4; mf++) {
#pragma unroll
            for (int half = 0; half < 2; half++) {
                const int m = mrow0 + wm0 + mf*16 + gid + half*8;
                const float v0 = acc[mf][nf][half*2 + 0] + bv0;
                const float v1 = acc[mf][nf][half*2 + 1] + bv1;
                if (qkv_layout) {
                    const int b_ = m >> 11, ns = m & (SEQ - 1);
                    *(float2*)&C[(((size_t)(b_*NHEAD + h))*SEQ + ns)*HD + d] =
                        make_float2(v0, v1);
                } else {
                    *(float2*)&C[(size_t)m*FEATS + col] = make_float2(v0, v1);
                }
            }
        }
    }
}

// ---------------------------------------------------------------------------
// Flash attention on mma.sync tf32.
// CTA: 128 queries x (b,h); 8 warps, 16 queries/warp; 64-key tiles; hd=64.
// Smem stride 72 floats -> all fragment loads conflict-free (8*gid+tg).
// K/V staged pre-converted to tf32. Q held in A-fragments for whole kernel.
// P routed through per-warp smem (frag layout mismatch), __syncwarp only.
// ---------------------------------------------------------------------------
#define ATS 72
#define ASM_K 0
#define ASM_V (64*ATS)
#define ASM_P (2*64*ATS)
#define ATT_BYTES ((2*64*ATS + 128*ATS) * 4)   // 73728

__global__ __launch_bounds__(256) void attn_mma_kernel(
    const float* __restrict__ Qg, const float* __restrict__ Kg,
    const float* __restrict__ Vg, float* __restrict__ Og)
{
    extern __shared__ __align__(16) float smf[];
    float* Ks = smf + ASM_K;
    float* Vs = smf + ASM_V;
    float* Ps = smf + ASM_P;

    const int tid  = threadIdx.x;
    const int wid  = tid >> 5, lane = tid & 31;
    const int gid  = lane >> 2, tg = lane & 3;
    const int wq   = wid * 16;           // warp's query offset in CTA tile

    const int bh = blockIdx.y;
    const int q0 = blockIdx.x * 128;
    const float* Qb = Qg + ((size_t)bh * SEQ + q0) * HD;
    const float* Kb = Kg + (size_t)bh * SEQ * HD;
    const float* Vb = Vg + (size_t)bh * SEQ * HD;
    const float scale = 1.0f / 32.0f;

    // ---- stage Q tile [128][64] into Ps (coalesced), then to A-frags ----
    for (int t = tid; t < 128*16; t += 256) {
        const int r = t >> 4, c4 = (t & 15) << 2;
        *(float4*)&Ps[r*ATS + c4] = *(const float4*)(Qb + r*HD + c4);
    }
    __syncthreads();

    uint32_t qa[8][4];
#pragma unroll
    for (int ks = 0; ks < 8; ks++) {
        const int k = ks*8 + tg;
        qa[ks][0] = f2tf32(Ps[(wq+gid  )*ATS + k    ] * scale);
        qa[ks][1] = f2tf32(Ps[(wq+gid+8)*ATS + k    ] * scale);
        qa[ks][2] = f2tf32(Ps[(wq+gid  )*ATS + k + 4] * scale);
        qa[ks][3] = f2tf32(Ps[(wq+gid+8)*ATS + k + 4] * scale);
    }

    float m0 = -1e30f, m1 = -1e30f, l0 = 0.0f, l1 = 0.0f;
    float oacc[8][4];
#pragma unroll
    for (int nf = 0; nf < 8; nf++)
#pragma unroll
        for (int q = 0; q < 4; q++) oacc[nf][q] = 0.0f;

    for (int kt = 0; kt < SEQ/64; kt++) {
        __syncthreads();   // prior-iter readers done with Ks/Vs; Ps safe (own warp)
        const float* Kt = Kb + (size_t)kt * 64 * HD;
        const float* Vt = Vb + (size_t)kt * 64 * HD;
        for (int t = tid; t < 64*16; t += 256) {
            const int r = t >> 4, c4 = (t & 15) << 2;
            float4 kv = *(const float4*)(Kt + r*HD + c4);
            float4 vv = *(const float4*)(Vt + r*HD + c4);
            kv.x = tf32f(kv.x); kv.y = tf32f(kv.y);
            kv.z = tf32f(kv.z); kv.w = tf32f(kv.w);
            vv.x = tf32f(vv.x); vv.y = tf32f(vv.y);
            vv.z = tf32f(vv.z); vv.w = tf32f(vv.w);
            *(float4*)&Ks[r*ATS + c4] = kv;
            *(float4*)&Vs[r*ATS + c4] = vv;
        }
        __syncthreads();

        // ---- S = Q K^T : 8 nfrags x 8 ksteps ----
        float sacc[8][4];
#pragma unroll
        for (int nf = 0; nf < 8; nf++)
#pragma unroll
            for (int q = 0; q < 4; q++) sacc[nf][q] = 0.0f;

#pragma unroll
        for (int ks = 0; ks < 8; ks++) {
            const int k = ks*8 + tg;
            uint32_t bb[8][2];
#pragma unroll
            for (int nf = 0; nf < 8; nf++) {
                const int n = nf*8 + gid;
                bb[nf][0] = __float_as_uint(Ks[n*ATS + k    ]);
                bb[nf][1] = __float_as_uint(Ks[n*ATS + k + 4]);
            }
#pragma unroll
            for (int nf = 0; nf < 8; nf++)
                mma_tf32(sacc[nf], qa[ks][0], qa[ks][1], qa[ks][2], qa[ks][3],
                         bb[nf][0], bb[nf][1]);
        }

        // ---- online softmax (rows wq+gid, wq+gid+8) ----
        float mt0 = -1e30f, mt1 = -1e30f;
#pragma unroll
        for (int nf = 0; nf < 8; nf++) {
            mt0 = fmaxf(mt0, fmaxf(sacc[nf][0], sacc[nf][1]));
            mt1 = fmaxf(mt1, fmaxf(sacc[nf][2], sacc[nf][3]));
        }
        mt0 = fmaxf(mt0, __shfl_xor_sync(0xffffffffu, mt0, 1));
        mt0 = fmaxf(mt0, __shfl_xor_sync(0xffffffffu, mt0, 2));
        mt1 = fmaxf(mt1, __shfl_xor_sync(0xffffffffu, mt1, 1));
        mt1 = fmaxf(mt1, __shfl_xor_sync(0xffffffffu, mt1, 2));
        const float mn0 = fmaxf(m0, mt0);
        const float mn1 = fmaxf(m1, mt1);

        float rs0 = 0.0f, rs1 = 0.0f;
#pragma unroll
        for (int nf = 0; nf < 8; nf++) {
            const float p00 = __expf(sacc[nf][0] - mn0);
            const float p01 = __expf(sacc[nf][1] - mn0);
            const float p10 = __expf(sacc[nf][2] - mn1);
            const float p11 = __expf(sacc[nf][3] - mn1);
            rs0 += p00 + p01;
            rs1 += p10 + p11;
            const int c = nf*8 + 2*tg;
            *(float2*)&Ps[(wq+gid  )*ATS + c] =
                make_float2(__uint_as_float(f2tf32(p00)), __uint_as_float(f2tf32(p01)));
            *(float2*)&Ps[(wq+gid+8)*ATS + c] =
                make_float2(__uint_as_float(f2tf32(p10)), __uint_as_float(f2tf32(p11)));
        }
        rs0 += __shfl_xor_sync(0xffffffffu, rs0, 1);
        rs0 += __shfl_xor_sync(0xffffffffu, rs0, 2);
        rs1 += __shfl_xor_sync(0xffffffffu, rs1, 1);
        rs1 += __shfl_xor_sync(0xffffffffu, rs1, 2);

        const float al0 = __expf(m0 - mn0);
        const float al1 = __expf(m1 - mn1);
        l0 = l0 * al0 + rs0;  m0 = mn0;
        l1 = l1 * al1 + rs1;  m1 = mn1;
#pragma unroll
        for (int nf = 0; nf < 8; nf++) {
            oacc[nf][0] *= al0; oacc[nf][1] *= al0;
            oacc[nf][2] *= al1; oacc[nf][3] *= al1;
        }
        __syncwarp();   // P stores visible to this warp's A-frag loads

        // ---- O += P V : k-dim = 64 keys ----
#pragma unroll
        for (int ks = 0; ks < 8; ks++) {
            const int k = ks*8 + tg;
            const uint32_t pa0 = __float_as_uint(Ps[(wq+gid  )*ATS + k    ]);
            const uint32_t pa1 = __float_as_uint(Ps[(wq+gid+8)*ATS + k    ]);
            const uint32_t pa2 = __float_as_uint(Ps[(wq+gid  )*ATS + k + 4]);
            const uint32_t pa3 = __float_as_uint(Ps[(wq+gid+8)*ATS + k + 4]);
#pragma unroll
            for (int nf = 0; nf < 8; nf++) {
                const int n = nf*8 + gid;
                const uint32_t bv0 = __float_as_uint(Vs[(k    )*ATS + n]);
                const uint32_t bv1 = __float_as_uint(Vs[(k + 4)*ATS + n]);
                mma_tf32(oacc[nf], pa0, pa1, pa2, pa3, bv0, bv1);
            }
        }
    }

    // ---- epilogue -> [b, n, h, d] ----
    const int b_ = bh >> 4, h = bh & 15;
    const float inv0 = 1.0f / l0, inv1 = 1.0f / l1;
    const int r0 = q0 + wq + gid, r1 = r0 + 8;
#pragma unroll
    for (int nf = 0; nf < 8; nf++) {
        const int d = nf*8 + 2*tg;
        *(float2*)&Og[(((size_t)b_*SEQ + r0)*NHEAD + h)*HD + d] =
            make_float2(oacc[nf][0]*inv0, oacc[nf][1]*inv0);
        *(float2*)&Og[(((size_t)b_*SEQ + r1)*NHEAD + h)*HD + d] =
            make_float2(oacc[nf][2]*inv1, oacc[nf][3]*inv1);
    }
}

// ---------------------------------------------------------------------------
extern "C" void kernel_launch(void* const* d_in, const int* in_sizes, int n_in,
                              void* d_out, int out_size)
{
    const float* x  = (const float*)d_in[0];
    const float* Wq = (const float*)d_in[1];
    const float* bq = (const float*)d_in[2];
    const float* Wk = (const float*)d_in[3];
    const float* bk = (const float*)d_in[4];
    const float* Wv = (const float*)d_in[5];
    const float* bv = (const float*)d_in[6];
    const float* Wo = (const float*)d_in[7];
    const float* bo = (const float*)d_in[8];
    float* out = (float*)d_out;

    float *Qb, *Kb, *Vb, *Ab;
    cudaGetSymbolAddress((void**)&Qb, g_Q);
    cudaGetSymbolAddress((void**)&Kb, g_K);
    cudaGetSymbolAddress((void**)&Vb, g_V);
    cudaGetSymbolAddress((void**)&Ab, g_A);

    cudaFuncSetAttribute(gemm_mma_kernel, cudaFuncAttributeMaxDynamicSharedMemorySize,
                         GSM_BYTES);
    cudaFuncSetAttribute(attn_mma_kernel, cudaFuncAttributeMaxDynamicSharedMemorySize,
                         ATT_BYTES);

    dim3 ggrid(MROWS/128, FEATS/128);   // (64, 8)
    gemm_mma_kernel<<<ggrid, 256, GSM_BYTES>>>(x, Wq, bq, Qb, 1);
    gemm_mma_kernel<<<ggrid, 256, GSM_BYTES>>>(x, Wk, bk, Kb, 1);
    gemm_mma_kernel<<<ggrid, 256, GSM_BYTES>>>(x, Wv, bv, Vb, 1);

    dim3 agrid(SEQ/128, BATCH*NHEAD);   // (16, 64)
    attn_mma_kernel<<<agrid, 256, ATT_BYTES>>>(Qb, Kb, Vb, Ab);

    gemm_mma_kernel<<<ggrid, 256, GSM_BYTES>>>(Ab, Wo, bo, out, 0);
}

// round 14
// speedup vs baseline: 3.0226x; 1.3961x over previous
#include <cuda_runtime.h>
#include <cstdint>
#include <math.h>

#define BATCH 4
#define SEQ   2048
#define FEATS 1024
#define NHEAD 16
#define HD    64
#define MROWS (BATCH*SEQ)

// ---------------- scratch (static device globals; no allocations) ----------
__device__ float g_Q[BATCH*NHEAD*SEQ*HD];   // [b,h,n,d]
__device__ float g_K[BATCH*NHEAD*SEQ*HD];
__device__ float g_V[BATCH*NHEAD*SEQ*HD];
__device__ float g_A[MROWS*FEATS];          // attention out, [b,n,h,d] == [m, f]

// ======================= portable PTX helpers (no 'a'-gated features) ======
__device__ __forceinline__ uint32_t smem_u32(const void* p) {
    uint32_t a;
    asm("{ .reg .u64 t; cvta.to.shared.u64 t, %1; cvt.u32.u64 %0, t; }"
        : "=r"(a) : "l"(p));
    return a;
}
#define CP_ASYNC16(saddr, gptr) \
    asm volatile("cp.async.cg.shared.global [%0], [%1], 16;" \
        :: "r"((uint32_t)(saddr)), "l"(gptr))
#define CP_COMMIT() asm volatile("cp.async.commit_group;" ::: "memory")
#define CP_WAIT(n)  asm volatile("cp.async.wait_group %0;" :: "n"(n) : "memory")

__device__ __forceinline__ uint32_t f2tf32(float f) {
    uint32_t r;
    asm("cvt.rna.tf32.f32 %0, %1;" : "=r"(r) : "f"(f));
    return r;
}
__device__ __forceinline__ float tf32f(float f) {
    uint32_t r = f2tf32(f);
    return __uint_as_float(r);
}
__device__ __forceinline__ void mma_tf32(float c[4], uint32_t a0, uint32_t a1,
                                         uint32_t a2, uint32_t a3,
                                         uint32_t b0, uint32_t b1) {
    asm volatile(
        "mma.sync.aligned.m16n8k8.row.col.f32.tf32.tf32.f32 "
        "{%0,%1,%2,%3}, {%4,%5,%6,%7}, {%8,%9}, {%0,%1,%2,%3};"
        : "+f"(c[0]), "+f"(c[1]), "+f"(c[2]), "+f"(c[3])
        : "r"(a0), "r"(a1), "r"(a2), "r"(a3), "r"(b0), "r"(b1));
}

// ---------------------------------------------------------------------------
// tf32 mma.sync GEMM (R12 pass, + forced 2 CTAs/SM):
// C[m, col] = sum_k X[m,k] * W[col,k] + bias[col]
// ---------------------------------------------------------------------------
#define KC   32
#define SS   36
#define BUFE (128*SS)
#define GSM_BYTES (4*BUFE*4)

__device__ __forceinline__ void stage_chunk(
    const float* __restrict__ X, const float* __restrict__ W,
    uint32_t sA, uint32_t sB, int mrow0, int ncol0, int k0, int tid)
{
    const int r0 = tid >> 2;
    const int f4 = tid & 3;
#pragma unroll
    for (int rr = 0; rr < 2; rr++) {
        const int r = r0 + rr*64;
#pragma unroll
        for (int ff = 0; ff < 2; ff++) {
            const int c = (f4 + ff*4) * 4;
            CP_ASYNC16(sA + (uint32_t)(r*SS + c)*4,
                       X + (size_t)(mrow0 + r)*FEATS + k0 + c);
            CP_ASYNC16(sB + (uint32_t)(r*SS + c)*4,
                       W + (size_t)(ncol0 + r)*FEATS + k0 + c);
        }
    }
}

__global__ __launch_bounds__(256, 2) void gemm_mma_kernel(
    const float* __restrict__ X, const float* __restrict__ W,
    const float* __restrict__ bias, float* __restrict__ C, int qkv_layout)
{
    extern __shared__ __align__(16) float smf[];
    const uint32_t smem_base = smem_u32(smf);

    const int tid  = threadIdx.x;
    const int wid  = tid >> 5, lane = tid & 31;
    const int gid  = lane >> 2, tg = lane & 3;
    const int wm0  = (wid & 1) * 64;
    const int wn0  = (wid >> 1) * 32;
    const int mrow0 = blockIdx.x * 128;
    const int ncol0 = blockIdx.y * 128;

    const uint32_t sA[2] = { smem_base,              smem_base + BUFE*4 };
    const uint32_t sB[2] = { smem_base + 2*BUFE*4,   smem_base + 3*BUFE*4 };
    const float*   fA[2] = { smf,          smf + BUFE };
    const float*   fB[2] = { smf + 2*BUFE, smf + 3*BUFE };

    float acc[4][4][4];
#pragma unroll
    for (int i = 0; i < 4; i++)
#pragma unroll
        for (int j = 0; j < 4; j++)
#pragma unroll
            for (int q = 0; q < 4; q++) acc[i][j][q] = 0.0f;

    stage_chunk(X, W, sA[0], sB[0], mrow0, ncol0, 0, tid);
    CP_COMMIT();

    for (int ck = 0; ck < FEATS/KC; ck++) {
        if (ck < FEATS/KC - 1) {
            stage_chunk(X, W, sA[(ck+1)&1], sB[(ck+1)&1],
                        mrow0, ncol0, (ck+1)*KC, tid);
            CP_COMMIT();
            CP_WAIT(1);
        } else {
            CP_WAIT(0);
        }
        __syncthreads();

        const float* As = fA[ck & 1];
        const float* Bs = fB[ck & 1];
#pragma unroll
        for (int kk = 0; kk < 4; kk++) {
            const int k = kk*8 + tg;
            uint32_t a[4][4];
#pragma unroll
            for (int mf = 0; mf < 4; mf++) {
                const int row = wm0 + mf*16 + gid;
                a[mf][0] = f2tf32(As[(row  )*SS + k    ]);
                a[mf][1] = f2tf32(As[(row+8)*SS + k    ]);
                a[mf][2] = f2tf32(As[(row  )*SS + k + 4]);
                a[mf][3] = f2tf32(As[(row+8)*SS + k + 4]);
            }
            uint32_t b[4][2];
#pragma unroll
            for (int nf = 0; nf < 4; nf++) {
                const int n = wn0 + nf*8 + gid;
                b[nf][0] = f2tf32(Bs[n*SS + k    ]);
                b[nf][1] = f2tf32(Bs[n*SS + k + 4]);
            }
#pragma unroll
            for (int mf = 0; mf < 4; mf++)
#pragma unroll
                for (int nf = 0; nf < 4; nf++)
                    mma_tf32(acc[mf][nf], a[mf][0], a[mf][1], a[mf][2], a[mf][3],
                             b[nf][0], b[nf][1]);
        }
        __syncthreads();
    }

#pragma unroll
    for (int nf = 0; nf < 4; nf++) {
        const int col = ncol0 + wn0 + nf*8 + 2*tg;
        const float bv0 = bias[col], bv1 = bias[col + 1];
        const int h = col >> 6, d = col & 63;
#pragma unroll
        for (int mf = 0; mf < 4; mf++) {
#pragma unroll
            for (int half = 0; half < 2; half++) {
                const int m = mrow0 + wm0 + mf*16 + gid + half*8;
                const float v0 = acc[mf][nf][half*2 + 0] + bv0;
                const float v1 = acc[mf][nf][half*2 + 1] + bv1;
                if (qkv_layout) {
                    const int b_ = m >> 11, ns = m & (SEQ - 1);
                    *(float2*)&C[(((size_t)(b_*NHEAD + h))*SEQ + ns)*HD + d] =
                        make_float2(v0, v1);
                } else {
                    *(float2*)&C[(size_t)m*FEATS + col] = make_float2(v0, v1);
                }
            }
        }
    }
}

// ---------------------------------------------------------------------------
// Flash attention on mma.sync tf32, v2:
//  - Q in dedicated smem (scale+tf32 folded at staging); frags re-read per
//    tile -> regs ~100, __launch_bounds__(256,2) -> 2 CTAs/SM (16 warps).
//  - Row swizzle RO(r)=r*72+(r&4): S/PV fragment loads conflict-free.
//  - Smem/CTA = 110.6KB (Qs 128x72, Ks/Vs 64x72, Ps 128x72).
// ---------------------------------------------------------------------------
#define ATS 72
#define RO(r) ((r)*ATS + ((r) & 4))
#define ASM_Q 0
#define ASM_K (128*ATS)
#define ASM_V (ASM_K + 64*ATS)
#define ASM_P (ASM_V + 64*ATS)
#define ATT_BYTES ((384*ATS) * 4)   // 110592

__global__ __launch_bounds__(256, 2) void attn_mma_kernel(
    const float* __restrict__ Qg, const float* __restrict__ Kg,
    const float* __restrict__ Vg, float* __restrict__ Og)
{
    extern __shared__ __align__(16) float smf[];
    float* Qs = smf + ASM_Q;
    float* Ks = smf + ASM_K;
    float* Vs = smf + ASM_V;
    float* Ps = smf + ASM_P;

    const int tid  = threadIdx.x;
    const int wid  = tid >> 5, lane = tid & 31;
    const int gid  = lane >> 2, tg = lane & 3;
    const int wq   = wid * 16;

    const int bh = blockIdx.y;
    const int q0 = blockIdx.x * 128;
    const float* Qb = Qg + ((size_t)bh * SEQ + q0) * HD;
    const float* Kb = Kg + (size_t)bh * SEQ * HD;
    const float* Vb = Vg + (size_t)bh * SEQ * HD;
    const float scale = 1.0f / 32.0f;

    // ---- stage Q tile [128][64]: scale + tf32, swizzled rows ----
    for (int t = tid; t < 128*16; t += 256) {
        const int r = t >> 4, c4 = (t & 15) << 2;
        float4 v = *(const float4*)(Qb + r*HD + c4);
        v.x = tf32f(v.x * scale); v.y = tf32f(v.y * scale);
        v.z = tf32f(v.z * scale); v.w = tf32f(v.w * scale);
        *(float4*)&Qs[RO(r) + c4] = v;
    }
    __syncthreads();

    const int qr0 = RO(wq + gid), qr1 = RO(wq + gid + 8);

    float m0 = -1e30f, m1 = -1e30f, l0 = 0.0f, l1 = 0.0f;
    float oacc[8][4];
#pragma unroll
    for (int nf = 0; nf < 8; nf++)
#pragma unroll
        for (int q = 0; q < 4; q++) oacc[nf][q] = 0.0f;

    for (int kt = 0; kt < SEQ/64; kt++) {
        __syncthreads();   // prior-iter PV readers done with Ks/Vs
        const float* Kt = Kb + (size_t)kt * 64 * HD;
        const float* Vt = Vb + (size_t)kt * 64 * HD;
        for (int t = tid; t < 64*16; t += 256) {
            const int r = t >> 4, c4 = (t & 15) << 2;
            float4 kv = *(const float4*)(Kt + r*HD + c4);
            float4 vv = *(const float4*)(Vt + r*HD + c4);
            kv.x = tf32f(kv.x); kv.y = tf32f(kv.y);
            kv.z = tf32f(kv.z); kv.w = tf32f(kv.w);
            vv.x = tf32f(vv.x); vv.y = tf32f(vv.y);
            vv.z = tf32f(vv.z); vv.w = tf32f(vv.w);
            *(float4*)&Ks[RO(r) + c4] = kv;
            *(float4*)&Vs[RO(r) + c4] = vv;
        }
        __syncthreads();

        // ---- S = Q K^T ----
        float sacc[8][4];
#pragma unroll
        for (int nf = 0; nf < 8; nf++)
#pragma unroll
            for (int q = 0; q < 4; q++) sacc[nf][q] = 0.0f;

#pragma unroll
        for (int ks = 0; ks < 8; ks++) {
            const int k = ks*8 + tg;
            const uint32_t qa0 = __float_as_uint(Qs[qr0 + k    ]);
            const uint32_t qa1 = __float_as_uint(Qs[qr1 + k    ]);
            const uint32_t qa2 = __float_as_uint(Qs[qr0 + k + 4]);
            const uint32_t qa3 = __float_as_uint(Qs[qr1 + k + 4]);
            uint32_t bb[8][2];
#pragma unroll
            for (int nf = 0; nf < 8; nf++) {
                const int n = nf*8 + gid;
                bb[nf][0] = __float_as_uint(Ks[RO(n) + k    ]);
                bb[nf][1] = __float_as_uint(Ks[RO(n) + k + 4]);
            }
#pragma unroll
            for (int nf = 0; nf < 8; nf++)
                mma_tf32(sacc[nf], qa0, qa1, qa2, qa3, bb[nf][0], bb[nf][1]);
        }

        // ---- online softmax (rows wq+gid, wq+gid+8) ----
        float mt0 = -1e30f, mt1 = -1e30f;
#pragma unroll
        for (int nf = 0; nf < 8; nf++) {
            mt0 = fmaxf(mt0, fmaxf(sacc[nf][0], sacc[nf][1]));
            mt1 = fmaxf(mt1, fmaxf(sacc[nf][2], sacc[nf][3]));
        }
        mt0 = fmaxf(mt0, __shfl_xor_sync(0xffffffffu, mt0, 1));
        mt0 = fmaxf(mt0, __shfl_xor_sync(0xffffffffu, mt0, 2));
        mt1 = fmaxf(mt1, __shfl_xor_sync(0xffffffffu, mt1, 1));
        mt1 = fmaxf(mt1, __shfl_xor_sync(0xffffffffu, mt1, 2));
        const float mn0 = fmaxf(m0, mt0);
        const float mn1 = fmaxf(m1, mt1);

        float rs0 = 0.0f, rs1 = 0.0f;
#pragma unroll
        for (int nf = 0; nf < 8; nf++) {
            const float p00 = __expf(sacc[nf][0] - mn0);
            const float p01 = __expf(sacc[nf][1] - mn0);
            const float p10 = __expf(sacc[nf][2] - mn1);
            const float p11 = __expf(sacc[nf][3] - mn1);
            rs0 += p00 + p01;
            rs1 += p10 + p11;
            const int c = nf*8 + 2*tg;
            *(float2*)&Ps[qr0 + c] =
                make_float2(__uint_as_float(f2tf32(p00)), __uint_as_float(f2tf32(p01)));
            *(float2*)&Ps[qr1 + c] =
                make_float2(__uint_as_float(f2tf32(p10)), __uint_as_float(f2tf32(p11)));
        }
        rs0 += __shfl_xor_sync(0xffffffffu, rs0, 1);
        rs0 += __shfl_xor_sync(0xffffffffu, rs0, 2);
        rs1 += __shfl_xor_sync(0xffffffffu, rs1, 1);
        rs1 += __shfl_xor_sync(0xffffffffu, rs1, 2);

        const float al0 = __expf(m0 - mn0);
        const float al1 = __expf(m1 - mn1);
        l0 = l0 * al0 + rs0;  m0 = mn0;
        l1 = l1 * al1 + rs1;  m1 = mn1;
#pragma unroll
        for (int nf = 0; nf < 8; nf++) {
            oacc[nf][0] *= al0; oacc[nf][1] *= al0;
            oacc[nf][2] *= al1; oacc[nf][3] *= al1;
        }
        __syncwarp();   // P stores visible to this warp's A-frag loads

        // ---- O += P V ----
#pragma unroll
        for (int ks = 0; ks < 8; ks++) {
            const int k = ks*8 + tg;
            const uint32_t pa0 = __float_as_uint(Ps[qr0 + k    ]);
            const uint32_t pa1 = __float_as_uint(Ps[qr1 + k    ]);
            const uint32_t pa2 = __float_as_uint(Ps[qr0 + k + 4]);
            const uint32_t pa3 = __float_as_uint(Ps[qr1 + k + 4]);
#pragma unroll
            for (int nf = 0; nf < 8; nf++) {
                const int n = nf*8 + gid;
                const uint32_t bv0 = __float_as_uint(Vs[RO(k    ) + n]);
                const uint32_t bv1 = __float_as_uint(Vs[RO(k + 4) + n]);
                mma_tf32(oacc[nf], pa0, pa1, pa2, pa3, bv0, bv1);
            }
        }
    }

    // ---- epilogue -> [b, n, h, d] ----
    const int b_ = bh >> 4, h = bh & 15;
    const float inv0 = 1.0f / l0, inv1 = 1.0f / l1;
    const int r0 = q0 + wq + gid, r1 = r0 + 8;
#pragma unroll
    for (int nf = 0; nf < 8; nf++) {
        const int d = nf*8 + 2*tg;
        *(float2*)&Og[(((size_t)b_*SEQ + r0)*NHEAD + h)*HD + d] =
            make_float2(oacc[nf][0]*inv0, oacc[nf][1]*inv0);
        *(float2*)&Og[(((size_t)b_*SEQ + r1)*NHEAD + h)*HD + d] =
            make_float2(oacc[nf][2]*inv1, oacc[nf][3]*inv1);
    }
}

// ---------------------------------------------------------------------------
extern "C" void kernel_launch(void* const* d_in, const int* in_sizes, int n_in,
                              void* d_out, int out_size)
{
    const float* x  = (const float*)d_in[0];
    const float* Wq = (const float*)d_in[1];
    const float* bq = (const float*)d_in[2];
    const float* Wk = (const float*)d_in[3];
    const float* bk = (const float*)d_in[4];
    const float* Wv = (const float*)d_in[5];
    const float* bv = (const float*)d_in[6];
    const float* Wo = (const float*)d_in[7];
    const float* bo = (const float*)d_in[8];
    float* out = (float*)d_out;

    float *Qb, *Kb, *Vb, *Ab;
    cudaGetSymbolAddress((void**)&Qb, g_Q);
    cudaGetSymbolAddress((void**)&Kb, g_K);
    cudaGetSymbolAddress((void**)&Vb, g_V);
    cudaGetSymbolAddress((void**)&Ab, g_A);

    cudaFuncSetAttribute(gemm_mma_kernel, cudaFuncAttributeMaxDynamicSharedMemorySize,
                         GSM_BYTES);
    cudaFuncSetAttribute(attn_mma_kernel, cudaFuncAttributeMaxDynamicSharedMemorySize,
                         ATT_BYTES);

    dim3 ggrid(MROWS/128, FEATS/128);   // (64, 8)
    gemm_mma_kernel<<<ggrid, 256, GSM_BYTES>>>(x, Wq, bq, Qb, 1);
    gemm_mma_kernel<<<ggrid, 256, GSM_BYTES>>>(x, Wk, bk, Kb, 1);
    gemm_mma_kernel<<<ggrid, 256, GSM_BYTES>>>(x, Wv, bv, Vb, 1);

    dim3 agrid(SEQ/128, BATCH*NHEAD);   // (16, 64)
    attn_mma_kernel<<<agrid, 256, ATT_BYTES>>>(Qb, Kb, Vb, Ab);

    gemm_mma_kernel<<<ggrid, 256, GSM_BYTES>>>(Ab, Wo, bo, out, 0);
}

// round 15
// speedup vs baseline: 3.4719x; 1.1486x over previous
#include <cuda_runtime.h>
#include <cuda_fp16.h>
#include <cstdint>
#include <math.h>

#define BATCH 4
#define SEQ   2048
#define FEATS 1024
#define NHEAD 16
#define HD    64
#define MROWS (BATCH*SEQ)

// ---------------- scratch (static device globals; no allocations) ----------
__device__ float g_Q[BATCH*NHEAD*SEQ*HD];   // [b,h,n,d]
__device__ float g_K[BATCH*NHEAD*SEQ*HD];
__device__ float g_V[BATCH*NHEAD*SEQ*HD];
__device__ float g_A[MROWS*FEATS];          // attention out, [b,n,h,d] == [m, f]

// ======================= portable PTX helpers (no 'a'-gated features) ======
__device__ __forceinline__ uint32_t smem_u32(const void* p) {
    uint32_t a;
    asm("{ .reg .u64 t; cvta.to.shared.u64 t, %1; cvt.u32.u64 %0, t; }"
        : "=r"(a) : "l"(p));
    return a;
}
#define CP_ASYNC16(saddr, gptr) \
    asm volatile("cp.async.cg.shared.global [%0], [%1], 16;" \
        :: "r"((uint32_t)(saddr)), "l"(gptr))
#define CP_COMMIT() asm volatile("cp.async.commit_group;" ::: "memory")
#define CP_WAIT(n)  asm volatile("cp.async.wait_group %0;" :: "n"(n) : "memory")

#define LDSM_X4(r0, r1, r2, r3, addr) \
    asm volatile("ldmatrix.sync.aligned.m8n8.x4.shared.b16 {%0,%1,%2,%3}, [%4];" \
        : "=r"(r0), "=r"(r1), "=r"(r2), "=r"(r3) : "r"(addr))
#define LDSM_X4_T(r0, r1, r2, r3, addr) \
    asm volatile("ldmatrix.sync.aligned.m8n8.x4.trans.shared.b16 {%0,%1,%2,%3}, [%4];" \
        : "=r"(r0), "=r"(r1), "=r"(r2), "=r"(r3) : "r"(addr))

__device__ __forceinline__ uint32_t packh2(float x, float y) {
    __half2 h = __floats2half2_rn(x, y);
    return *(uint32_t*)&h;
}
__device__ __forceinline__ void mma_f16(float c[4], uint32_t a0, uint32_t a1,
                                        uint32_t a2, uint32_t a3,
                                        uint32_t b0, uint32_t b1) {
    asm volatile(
        "mma.sync.aligned.m16n8k16.row.col.f32.f16.f16.f32 "
        "{%0,%1,%2,%3}, {%4,%5,%6,%7}, {%8,%9}, {%0,%1,%2,%3};"
        : "+f"(c[0]), "+f"(c[1]), "+f"(c[2]), "+f"(c[3])
        : "r"(a0), "r"(a1), "r"(a2), "r"(a3), "r"(b0), "r"(b1));
}

// ---------------------------------------------------------------------------
// fp16 mma.sync GEMM: C[m, col] = sum_k X[m,k] * W[col,k] + bias[col]
// Staging unchanged (cp.async f32, double buffer); inner loop = float2 loads
// + pack to half2, m16n8k16 mma (half the mma count of tf32 k8).
// ---------------------------------------------------------------------------
#define KC   32
#define SS   36
#define BUFE (128*SS)
#define GSM_BYTES (4*BUFE*4)

__device__ __forceinline__ void stage_chunk(
    const float* __restrict__ X, const float* __restrict__ W,
    uint32_t sA, uint32_t sB, int mrow0, int ncol0, int k0, int tid)
{
    const int r0 = tid >> 2;
    const int f4 = tid & 3;
#pragma unroll
    for (int rr = 0; rr < 2; rr++) {
        const int r = r0 + rr*64;
#pragma unroll
        for (int ff = 0; ff < 2; ff++) {
            const int c = (f4 + ff*4) * 4;
            CP_ASYNC16(sA + (uint32_t)(r*SS + c)*4,
                       X + (size_t)(mrow0 + r)*FEATS + k0 + c);
            CP_ASYNC16(sB + (uint32_t)(r*SS + c)*4,
                       W + (size_t)(ncol0 + r)*FEATS + k0 + c);
        }
    }
}

__global__ __launch_bounds__(256, 2) void gemm_mma_kernel(
    const float* __restrict__ X, const float* __restrict__ W,
    const float* __restrict__ bias, float* __restrict__ C, int qkv_layout)
{
    extern __shared__ __align__(16) float smf[];
    const uint32_t smem_base = smem_u32(smf);

    const int tid  = threadIdx.x;
    const int wid  = tid >> 5, lane = tid & 31;
    const int gid  = lane >> 2, tg = lane & 3;
    const int wm0  = (wid & 1) * 64;
    const int wn0  = (wid >> 1) * 32;
    const int mrow0 = blockIdx.x * 128;
    const int ncol0 = blockIdx.y * 128;

    const uint32_t sA[2] = { smem_base,              smem_base + BUFE*4 };
    const uint32_t sB[2] = { smem_base + 2*BUFE*4,   smem_base + 3*BUFE*4 };
    const float*   fA[2] = { smf,          smf + BUFE };
    const float*   fB[2] = { smf + 2*BUFE, smf + 3*BUFE };

    float acc[4][4][4];
#pragma unroll
    for (int i = 0; i < 4; i++)
#pragma unroll
        for (int j = 0; j < 4; j++)
#pragma unroll
            for (int q = 0; q < 4; q++) acc[i][j][q] = 0.0f;

    stage_chunk(X, W, sA[0], sB[0], mrow0, ncol0, 0, tid);
    CP_COMMIT();

    for (int ck = 0; ck < FEATS/KC; ck++) {
        if (ck < FEATS/KC - 1) {
            stage_chunk(X, W, sA[(ck+1)&1], sB[(ck+1)&1],
                        mrow0, ncol0, (ck+1)*KC, tid);
            CP_COMMIT();
            CP_WAIT(1);
        } else {
            CP_WAIT(0);
        }
        __syncthreads();

        const float* As = fA[ck & 1];
        const float* Bs = fB[ck & 1];
#pragma unroll
        for (int kk = 0; kk < 2; kk++) {
            const int k = kk*16 + 2*tg;
            uint32_t a[4][4];
#pragma unroll
            for (int mf = 0; mf < 4; mf++) {
                const int row = wm0 + mf*16 + gid;
                float2 x0 = *(const float2*)&As[(row  )*SS + k    ];
                float2 x1 = *(const float2*)&As[(row+8)*SS + k    ];
                float2 x2 = *(const float2*)&As[(row  )*SS + k + 8];
                float2 x3 = *(const float2*)&As[(row+8)*SS + k + 8];
                a[mf][0] = packh2(x0.x, x0.y);
                a[mf][1] = packh2(x1.x, x1.y);
                a[mf][2] = packh2(x2.x, x2.y);
                a[mf][3] = packh2(x3.x, x3.y);
            }
            uint32_t b[4][2];
#pragma unroll
            for (int nf = 0; nf < 4; nf++) {
                const int n = wn0 + nf*8 + gid;
                float2 y0 = *(const float2*)&Bs[n*SS + k    ];
                float2 y1 = *(const float2*)&Bs[n*SS + k + 8];
                b[nf][0] = packh2(y0.x, y0.y);
                b[nf][1] = packh2(y1.x, y1.y);
            }
#pragma unroll
            for (int mf = 0; mf < 4; mf++)
#pragma unroll
                for (int nf = 0; nf < 4; nf++)
                    mma_f16(acc[mf][nf], a[mf][0], a[mf][1], a[mf][2], a[mf][3],
                            b[nf][0], b[nf][1]);
        }
        __syncthreads();
    }

#pragma unroll
    for (int nf = 0; nf < 4; nf++) {
        const int col = ncol0 + wn0 + nf*8 + 2*tg;
        const float bv0 = bias[col], bv1 = bias[col + 1];
        const int h = col >> 6, d = col & 63;
#pragma unroll
        for (int mf = 0; mf < 4; mf++) {
#pragma unroll
            for (int half = 0; half < 2; half++) {
                const int m = mrow0 + wm0 + mf*16 + gid + half*8;
                const float v0 = acc[mf][nf][half*2 + 0] + bv0;
                const float v1 = acc[mf][nf][half*2 + 1] + bv1;
                if (qkv_layout) {
                    const int b_ = m >> 11, ns = m & (SEQ - 1);
                    *(float2*)&C[(((size_t)(b_*NHEAD + h))*SEQ + ns)*HD + d] =
                        make_float2(v0, v1);
                } else {
                    *(float2*)&C[(size_t)m*FEATS + col] = make_float2(v0, v1);
                }
            }
        }
    }
}

// ---------------------------------------------------------------------------
// Flash attention, fp16 operands + ldmatrix:
//  - Q/K/V/P in __half smem, converted at staging (no inner-loop cvt).
//  - All fragments via ldmatrix.x4; V via ldmatrix.x4.trans (HW transpose).
//  - Stride 72 halfs: ldmatrix rows land on banks 4r..4r+3, conflict-free.
//  - Smem 55296 B/CTA, 2 CTAs/SM.
// ---------------------------------------------------------------------------
#define AH 72
#define ATT_BYTES (384*AH*2)   // 55296

__global__ __launch_bounds__(256, 2) void attn_f16_kernel(
    const float* __restrict__ Qg, const float* __restrict__ Kg,
    const float* __restrict__ Vg, float* __restrict__ Og)
{
    extern __shared__ __align__(16) __half smh[];
    __half* Qs = smh;                  // [128][AH]
    __half* Ks = smh + 128*AH;         // [64 key][AH d]
    __half* Vs = Ks + 64*AH;           // [64 key][AH d]
    __half* Ps = Vs + 64*AH;           // [128][AH key]

    const int tid  = threadIdx.x;
    const int wid  = tid >> 5, lane = tid & 31;
    const int gid  = lane >> 2, tg = lane & 3;
    const int wq   = wid * 16;
    const int l7   = lane & 7;

    const int bh = blockIdx.y;
    const int q0 = blockIdx.x * 128;
    const float* Qb = Qg + ((size_t)bh * SEQ + q0) * HD;
    const float* Kb = Kg + (size_t)bh * SEQ * HD;
    const float* Vb = Vg + (size_t)bh * SEQ * HD;
    const float scale = 1.0f / 32.0f;

    // ---- stage Q [128][64] as half (scale folded) ----
    for (int t = tid; t < 128*16; t += 256) {
        const int r = t >> 4, c4 = (t & 15) << 2;
        float4 v = *(const float4*)(Qb + r*HD + c4);
        uint2 u = make_uint2(packh2(v.x*scale, v.y*scale),
                             packh2(v.z*scale, v.w*scale));
        *(uint2*)&Qs[r*AH + c4] = u;
    }
    __syncthreads();

    // ldmatrix per-lane base addresses (byte units)
    const uint32_t aQ = smem_u32(&Qs[(wq + l7 + (lane & 8))*AH + ((lane >> 4) << 3)]);
    const uint32_t aP = smem_u32(&Ps[(wq + l7 + (lane & 8))*AH + ((lane >> 4) << 3)]);
    const uint32_t aK = smem_u32(&Ks[(l7 + ((lane >> 1) & 8))*AH + (lane & 8)]);
    const uint32_t aV = smem_u32(&Vs[(l7 + (lane & 8))*AH + ((lane >> 1) & 8)]);

    float m0 = -1e30f, m1 = -1e30f, l0 = 0.0f, l1 = 0.0f;
    float oacc[8][4];
#pragma unroll
    for (int nf = 0; nf < 8; nf++)
#pragma unroll
        for (int q = 0; q < 4; q++) oacc[nf][q] = 0.0f;

    for (int kt = 0; kt < SEQ/64; kt++) {
        __syncthreads();   // prior-iter readers done with Ks/Vs
        const float* Kt = Kb + (size_t)kt * 64 * HD;
        const float* Vt = Vb + (size_t)kt * 64 * HD;
        for (int t = tid; t < 64*16; t += 256) {
            const int r = t >> 4, c4 = (t & 15) << 2;
            float4 kv = *(const float4*)(Kt + r*HD + c4);
            float4 vv = *(const float4*)(Vt + r*HD + c4);
            *(uint2*)&Ks[r*AH + c4] = make_uint2(packh2(kv.x, kv.y), packh2(kv.z, kv.w));
            *(uint2*)&Vs[r*AH + c4] = make_uint2(packh2(vv.x, vv.y), packh2(vv.z, vv.w));
        }
        __syncthreads();

        // ---- S = Q K^T : 4 k16-steps over d ----
        float sacc[8][4];
#pragma unroll
        for (int nf = 0; nf < 8; nf++)
#pragma unroll
            for (int q = 0; q < 4; q++) sacc[nf][q] = 0.0f;

#pragma unroll
        for (int ks = 0; ks < 4; ks++) {
            uint32_t qa0, qa1, qa2, qa3;
            LDSM_X4(qa0, qa1, qa2, qa3, aQ + ks*32);
#pragma unroll
            for (int np = 0; np < 4; np++) {
                uint32_t b0, b1, b2, b3;
                LDSM_X4(b0, b1, b2, b3, aK + np*2304 + ks*32);
                mma_f16(sacc[2*np    ], qa0, qa1, qa2, qa3, b0, b1);
                mma_f16(sacc[2*np + 1], qa0, qa1, qa2, qa3, b2, b3);
            }
        }

        // ---- online softmax (rows wq+gid, wq+gid+8) ----
        float mt0 = -1e30f, mt1 = -1e30f;
#pragma unroll
        for (int nf = 0; nf < 8; nf++) {
            mt0 = fmaxf(mt0, fmaxf(sacc[nf][0], sacc[nf][1]));
            mt1 = fmaxf(mt1, fmaxf(sacc[nf][2], sacc[nf][3]));
        }
        mt0 = fmaxf(mt0, __shfl_xor_sync(0xffffffffu, mt0, 1));
        mt0 = fmaxf(mt0, __shfl_xor_sync(0xffffffffu, mt0, 2));
        mt1 = fmaxf(mt1, __shfl_xor_sync(0xffffffffu, mt1, 1));
        mt1 = fmaxf(mt1, __shfl_xor_sync(0xffffffffu, mt1, 2));
        const float mn0 = fmaxf(m0, mt0);
        const float mn1 = fmaxf(m1, mt1);

        float rs0 = 0.0f, rs1 = 0.0f;
#pragma unroll
        for (int nf = 0; nf < 8; nf++) {
            const float p00 = __expf(sacc[nf][0] - mn0);
            const float p01 = __expf(sacc[nf][1] - mn0);
            const float p10 = __expf(sacc[nf][2] - mn1);
            const float p11 = __expf(sacc[nf][3] - mn1);
            rs0 += p00 + p01;
            rs1 += p10 + p11;
            const int c = nf*8 + 2*tg;
            *(__half2*)&Ps[(wq+gid  )*AH + c] = __floats2half2_rn(p00, p01);
            *(__half2*)&Ps[(wq+gid+8)*AH + c] = __floats2half2_rn(p10, p11);
        }
        rs0 += __shfl_xor_sync(0xffffffffu, rs0, 1);
        rs0 += __shfl_xor_sync(0xffffffffu, rs0, 2);
        rs1 += __shfl_xor_sync(0xffffffffu, rs1, 1);
        rs1 += __shfl_xor_sync(0xffffffffu, rs1, 2);

        const float al0 = __expf(m0 - mn0);
        const float al1 = __expf(m1 - mn1);
        l0 = l0 * al0 + rs0;  m0 = mn0;
        l1 = l1 * al1 + rs1;  m1 = mn1;
#pragma unroll
        for (int nf = 0; nf < 8; nf++) {
            oacc[nf][0] *= al0; oacc[nf][1] *= al0;
            oacc[nf][2] *= al1; oacc[nf][3] *= al1;
        }
        __syncwarp();   // P stores visible to this warp's ldmatrix

        // ---- O += P V : 4 k16-steps over keys; V transposed by ldmatrix ----
#pragma unroll
        for (int ks = 0; ks < 4; ks++) {
            uint32_t pa0, pa1, pa2, pa3;
            LDSM_X4(pa0, pa1, pa2, pa3, aP + ks*32);
#pragma unroll
            for (int np = 0; np < 4; np++) {
                uint32_t v0, v1, v2, v3;
                LDSM_X4_T(v0, v1, v2, v3, aV + ks*2304 + np*32);
                mma_f16(oacc[2*np    ], pa0, pa1, pa2, pa3, v0, v1);
                mma_f16(oacc[2*np + 1], pa0, pa1, pa2, pa3, v2, v3);
            }
        }
    }

    // ---- epilogue -> [b, n, h, d] ----
    const int b_ = bh >> 4, h = bh & 15;
    const float inv0 = 1.0f / l0, inv1 = 1.0f / l1;
    const int r0 = q0 + wq + gid, r1 = r0 + 8;
#pragma unroll
    for (int nf = 0; nf < 8; nf++) {
        const int d = nf*8 + 2*tg;
        *(float2*)&Og[(((size_t)b_*SEQ + r0)*NHEAD + h)*HD + d] =
            make_float2(oacc[nf][0]*inv0, oacc[nf][1]*inv0);
        *(float2*)&Og[(((size_t)b_*SEQ + r1)*NHEAD + h)*HD + d] =
            make_float2(oacc[nf][2]*inv1, oacc[nf][3]*inv1);
    }
}

// ---------------------------------------------------------------------------
extern "C" void kernel_launch(void* const* d_in, const int* in_sizes, int n_in,
                              void* d_out, int out_size)
{
    const float* x  = (const float*)d_in[0];
    const float* Wq = (const float*)d_in[1];
    const float* bq = (const float*)d_in[2];
    const float* Wk = (const float*)d_in[3];
    const float* bk = (const float*)d_in[4];
    const float* Wv = (const float*)d_in[5];
    const float* bv = (const float*)d_in[6];
    const float* Wo = (const float*)d_in[7];
    const float* bo = (const float*)d_in[8];
    float* out = (float*)d_out;

    float *Qb, *Kb, *Vb, *Ab;
    cudaGetSymbolAddress((void**)&Qb, g_Q);
    cudaGetSymbolAddress((void**)&Kb, g_K);
    cudaGetSymbolAddress((void**)&Vb, g_V);
    cudaGetSymbolAddress((void**)&Ab, g_A);

    cudaFuncSetAttribute(gemm_mma_kernel, cudaFuncAttributeMaxDynamicSharedMemorySize,
                         GSM_BYTES);
    cudaFuncSetAttribute(attn_f16_kernel, cudaFuncAttributeMaxDynamicSharedMemorySize,
                         ATT_BYTES);

    dim3 ggrid(MROWS/128, FEATS/128);   // (64, 8)
    gemm_mma_kernel<<<ggrid, 256, GSM_BYTES>>>(x, Wq, bq, Qb, 1);
    gemm_mma_kernel<<<ggrid, 256, GSM_BYTES>>>(x, Wk, bk, Kb, 1);
    gemm_mma_kernel<<<ggrid, 256, GSM_BYTES>>>(x, Wv, bv, Vb, 1);

    dim3 agrid(SEQ/128, BATCH*NHEAD);   // (16, 64)
    attn_f16_kernel<<<agrid, 256, ATT_BYTES>>>(Qb, Kb, Vb, Ab);

    gemm_mma_kernel<<<ggrid, 256, GSM_BYTES>>>(Ab, Wo, bo, out, 0);
}

// round 16
// speedup vs baseline: 7.1224x; 2.0515x over previous
#include <cuda_runtime.h>
#include <cuda_fp16.h>
#include <cstdint>
#include <math.h>

#define BATCH 4
#define SEQ   2048
#define FEATS 1024
#define NHEAD 16
#define HD    64
#define MROWS (BATCH*SEQ)

// ---------------- scratch (static device globals; no allocations) ----------
__device__ __half g_Xh[MROWS*FEATS];
__device__ __half g_Wqh[FEATS*FEATS];
__device__ __half g_Wkh[FEATS*FEATS];
__device__ __half g_Wvh[FEATS*FEATS];
__device__ __half g_Woh[FEATS*FEATS];
__device__ __half g_Qh[BATCH*NHEAD*SEQ*HD];   // [b,h,n,d], pre-scaled by 1/32
__device__ __half g_Kh[BATCH*NHEAD*SEQ*HD];
__device__ __half g_Vh[BATCH*NHEAD*SEQ*HD];
__device__ __half g_Ah[MROWS*FEATS];          // attention out, [b,n,h,d]

// ======================= portable PTX helpers ==============================
__device__ __forceinline__ uint32_t smem_u32(const void* p) {
    uint32_t a;
    asm("{ .reg .u64 t; cvta.to.shared.u64 t, %1; cvt.u32.u64 %0, t; }"
        : "=r"(a) : "l"(p));
    return a;
}
#define CP_ASYNC16(saddr, gptr) \
    asm volatile("cp.async.cg.shared.global [%0], [%1], 16;" \
        :: "r"((uint32_t)(saddr)), "l"(gptr))
#define CP_COMMIT() asm volatile("cp.async.commit_group;" ::: "memory")
#define CP_WAIT(n)  asm volatile("cp.async.wait_group %0;" :: "n"(n) : "memory")

#define LDSM_X4(r0, r1, r2, r3, addr) \
    asm volatile("ldmatrix.sync.aligned.m8n8.x4.shared.b16 {%0,%1,%2,%3}, [%4];" \
        : "=r"(r0), "=r"(r1), "=r"(r2), "=r"(r3) : "r"(addr))
#define LDSM_X4_T(r0, r1, r2, r3, addr) \
    asm volatile("ldmatrix.sync.aligned.m8n8.x4.trans.shared.b16 {%0,%1,%2,%3}, [%4];" \
        : "=r"(r0), "=r"(r1), "=r"(r2), "=r"(r3) : "r"(addr))

__device__ __forceinline__ uint32_t packh2(float x, float y) {
    __half2 h = __floats2half2_rn(x, y);
    return *(uint32_t*)&h;
}
__device__ __forceinline__ void mma_f16(float c[4], uint32_t a0, uint32_t a1,
                                        uint32_t a2, uint32_t a3,
                                        uint32_t b0, uint32_t b1) {
    asm volatile(
        "mma.sync.aligned.m16n8k16.row.col.f32.f16.f16.f32 "
        "{%0,%1,%2,%3}, {%4,%5,%6,%7}, {%8,%9}, {%0,%1,%2,%3};"
        : "+f"(c[0]), "+f"(c[1]), "+f"(c[2]), "+f"(c[3])
        : "r"(a0), "r"(a1), "r"(a2), "r"(a3), "r"(b0), "r"(b1));
}

// ---------------------------------------------------------------------------
// fp32 -> fp16 convert (vectorized)
// ---------------------------------------------------------------------------
__global__ __launch_bounds__(256) void cvt_kernel(const float4* __restrict__ src,
                                                  uint2* __restrict__ dst, int n4)
{
    int i = blockIdx.x*256 + threadIdx.x;
    if (i < n4) {
        float4 v = src[i];
        dst[i] = make_uint2(packh2(v.x, v.y), packh2(v.z, v.w));
    }
}

// ---------------------------------------------------------------------------
// fp16-in GEMM: C[m, col] = sum_k X[m,k] * W[col,k] + bias[col]
// half operands staged by cp.async, ldmatrix fragments, m16n8k16 mma.
// K chunk 64 halfs (128B rows), double buffered. Smem stride 72 halfs.
// layout: 0 -> float out [m,f]; 1 -> half out [b,h,n,d]; 2 -> same + *1/32.
// ---------------------------------------------------------------------------
#define SH 72
#define GBUFB (128*SH*2)          // bytes per tile buffer = 18432
#define GSMB  (4*GBUFB)           // 73728

__device__ __forceinline__ void stage_h(
    const __half* __restrict__ X, const __half* __restrict__ W,
    uint32_t sA, uint32_t sB, int mrow0, int ncol0, int k0, int tid)
{
    const int r0 = tid >> 2, c = tid & 3;
#pragma unroll
    for (int rr = 0; rr < 2; rr++) {
        const int r = r0 + rr*64;
#pragma unroll
        for (int ff = 0; ff < 2; ff++) {
            const int c16 = c + ff*4;
            CP_ASYNC16(sA + (uint32_t)(r*SH + c16*8)*2,
                       X + (size_t)(mrow0 + r)*FEATS + k0 + c16*8);
            CP_ASYNC16(sB + (uint32_t)(r*SH + c16*8)*2,
                       W + (size_t)(ncol0 + r)*FEATS + k0 + c16*8);
        }
    }
}

__global__ __launch_bounds__(256, 2) void gemm_h_kernel(
    const __half* __restrict__ X, const __half* __restrict__ W,
    const float* __restrict__ bias, float* __restrict__ Cf,
    __half* __restrict__ Ch, int layout)
{
    extern __shared__ __align__(16) __half smh[];
    const uint32_t smem_base = smem_u32(smh);

    const int tid  = threadIdx.x;
    const int wid  = tid >> 5, lane = tid & 31;
    const int gid  = lane >> 2, tg = lane & 3;
    const int l7   = lane & 7;
    const int wm0  = (wid & 1) * 64;
    const int wn0  = (wid >> 1) * 32;
    const int mrow0 = blockIdx.x * 128;
    const int ncol0 = blockIdx.y * 128;

    const uint32_t sA0 = smem_base;
    const uint32_t sB0 = smem_base + 2*GBUFB;

    // ldmatrix lane bases (buffer 0; add buf*GBUFB)
    const uint32_t aA0 = smem_u32(&smh[(wm0 + l7 + (lane & 8))*SH + ((lane >> 4) << 3)]);
    const uint32_t aB0 = smem_u32(&smh[2*128*SH + (wn0 + l7 + ((lane >> 1) & 8))*SH + (lane & 8)]);

    float acc[4][4][4];
#pragma unroll
    for (int i = 0; i < 4; i++)
#pragma unroll
        for (int j = 0; j < 4; j++)
#pragma unroll
            for (int q = 0; q < 4; q++) acc[i][j][q] = 0.0f;

    stage_h(X, W, sA0, sB0, mrow0, ncol0, 0, tid);
    CP_COMMIT();

    for (int ck = 0; ck < FEATS/64; ck++) {
        const int buf = ck & 1;
        if (ck < FEATS/64 - 1) {
            const int nb = (ck+1) & 1;
            stage_h(X, W, sA0 + nb*GBUFB, sB0 + nb*GBUFB,
                    mrow0, ncol0, (ck+1)*64, tid);
            CP_COMMIT();
            CP_WAIT(1);
        } else {
            CP_WAIT(0);
        }
        __syncthreads();

        const uint32_t aA = aA0 + buf*GBUFB;
        const uint32_t aB = aB0 + buf*GBUFB;
#pragma unroll
        for (int ks = 0; ks < 4; ks++) {
            uint32_t a[4][4];
#pragma unroll
            for (int mf = 0; mf < 4; mf++)
                LDSM_X4(a[mf][0], a[mf][1], a[mf][2], a[mf][3],
                        aA + mf*(16*SH*2) + ks*32);
#pragma unroll
            for (int nh = 0; nh < 2; nh++) {
                uint32_t b0, b1, b2, b3;
                LDSM_X4(b0, b1, b2, b3, aB + nh*(16*SH*2) + ks*32);
#pragma unroll
                for (int mf = 0; mf < 4; mf++) {
                    mma_f16(acc[mf][2*nh    ], a[mf][0], a[mf][1], a[mf][2], a[mf][3], b0, b1);
                    mma_f16(acc[mf][2*nh + 1], a[mf][0], a[mf][1], a[mf][2], a[mf][3], b2, b3);
                }
            }
        }
        __syncthreads();
    }

    const float osc = (layout == 2) ? (1.0f/32.0f) : 1.0f;
#pragma unroll
    for (int nf = 0; nf < 4; nf++) {
        const int col = ncol0 + wn0 + nf*8 + 2*tg;
        const float bv0 = bias[col], bv1 = bias[col + 1];
        const int h = col >> 6, d = col & 63;
#pragma unroll
        for (int mf = 0; mf < 4; mf++) {
#pragma unroll
            for (int half = 0; half < 2; half++) {
                const int m = mrow0 + wm0 + mf*16 + gid + half*8;
                const float v0 = (acc[mf][nf][half*2 + 0] + bv0) * osc;
                const float v1 = (acc[mf][nf][half*2 + 1] + bv1) * osc;
                if (layout) {
                    const int b_ = m >> 11, ns = m & (SEQ - 1);
                    *(__half2*)&Ch[(((size_t)(b_*NHEAD + h))*SEQ + ns)*HD + d] =
                        __floats2half2_rn(v0, v1);
                } else {
                    *(float2*)&Cf[(size_t)m*FEATS + col] = make_float2(v0, v1);
                }
            }
        }
    }
}

// ---------------------------------------------------------------------------
// Flash attention, all-half staging via cp.async, double-buffered K/V.
// Smem rows (stride AH=72 halfs): Q:0-127, K0:128-191, K1:192-255,
// V0:256-319, V1:320-383, P:384-511.  73728 B, 2 CTAs/SM.
// ---------------------------------------------------------------------------
#define AH 72
#define KVBUFB (64*AH*2)            // 9216 bytes per K/V buffer
#define ATT_BYTES (512*AH*2)        // 73728

__global__ __launch_bounds__(256, 2) void attn_h_kernel(
    const __half* __restrict__ Qg, const __half* __restrict__ Kg,
    const __half* __restrict__ Vg, __half* __restrict__ Og)
{
    extern __shared__ __align__(16) __half smh[];
    __half* Qs = smh;                       // [128][AH]
    __half* Ps = smh + 384*AH;              // [128][AH]
    const uint32_t sQ  = smem_u32(smh);
    const uint32_t sK0 = sQ + 128*AH*2;
    const uint32_t sV0 = sQ + 256*AH*2;

    const int tid  = threadIdx.x;
    const int wid  = tid >> 5, lane = tid & 31;
    const int gid  = lane >> 2, tg = lane & 3;
    const int wq   = wid * 16;
    const int l7   = lane & 7;

    const int bh = blockIdx.y;
    const int q0 = blockIdx.x * 128;
    const __half* Qb = Qg + ((size_t)bh * SEQ + q0) * HD;
    const __half* Kb = Kg + (size_t)bh * SEQ * HD;
    const __half* Vb = Vg + (size_t)bh * SEQ * HD;

    // ldmatrix lane bases
    const uint32_t aQ  = smem_u32(&Qs[(wq + l7 + (lane & 8))*AH + ((lane >> 4) << 3)]);
    const uint32_t aP  = smem_u32(&Ps[(wq + l7 + (lane & 8))*AH + ((lane >> 4) << 3)]);
    const uint32_t aK0 = sK0 + ((l7 + ((lane >> 1) & 8))*AH + (lane & 8))*2;
    const uint32_t aV0 = sV0 + ((l7 + (lane & 8))*AH + ((lane >> 1) & 8))*2;

    // ---- stage Q (cp.async straight copy, already scaled) ----
    {
        const int r = tid >> 1, c = tid & 1;
#pragma unroll
        for (int j = 0; j < 4; j++) {
            const int c16 = c + j*2;
            CP_ASYNC16(sQ + (uint32_t)(r*AH + c16*8)*2, Qb + r*HD + c16*8);
        }
    }
    // ---- stage K/V tile 0 into buffer 0 ----
    {
        const int r = tid >> 2, c = tid & 3;
#pragma unroll
        for (int j = 0; j < 2; j++) {
            const int c16 = c + j*4;
            CP_ASYNC16(sK0 + (uint32_t)(r*AH + c16*8)*2, Kb + r*HD + c16*8);
            CP_ASYNC16(sV0 + (uint32_t)(r*AH + c16*8)*2, Vb + r*HD + c16*8);
        }
    }
    CP_COMMIT();

    float m0 = -1e30f, m1 = -1e30f, l0 = 0.0f, l1 = 0.0f;
    float oacc[8][4];
#pragma unroll
    for (int nf = 0; nf < 8; nf++)
#pragma unroll
        for (int q = 0; q < 4; q++) oacc[nf][q] = 0.0f;

    for (int kt = 0; kt < SEQ/64; kt++) {
        const int buf = kt & 1;
        CP_WAIT(0);
        __syncthreads();

        if (kt < SEQ/64 - 1) {
            const int nb = (kt+1) & 1;
            const __half* Kt = Kb + (size_t)(kt+1) * 64 * HD;
            const __half* Vt = Vb + (size_t)(kt+1) * 64 * HD;
            const int r = tid >> 2, c = tid & 3;
#pragma unroll
            for (int j = 0; j < 2; j++) {
                const int c16 = c + j*4;
                CP_ASYNC16(sK0 + nb*KVBUFB + (uint32_t)(r*AH + c16*8)*2, Kt + r*HD + c16*8);
                CP_ASYNC16(sV0 + nb*KVBUFB + (uint32_t)(r*AH + c16*8)*2, Vt + r*HD + c16*8);
            }
            CP_COMMIT();
        }

        const uint32_t aK = aK0 + buf*KVBUFB;
        const uint32_t aV = aV0 + buf*KVBUFB;

        // ---- S = Q K^T ----
        float sacc[8][4];
#pragma unroll
        for (int nf = 0; nf < 8; nf++)
#pragma unroll
            for (int q = 0; q < 4; q++) sacc[nf][q] = 0.0f;

#pragma unroll
        for (int ks = 0; ks < 4; ks++) {
            uint32_t qa0, qa1, qa2, qa3;
            LDSM_X4(qa0, qa1, qa2, qa3, aQ + ks*32);
#pragma unroll
            for (int np = 0; np < 4; np++) {
                uint32_t b0, b1, b2, b3;
                LDSM_X4(b0, b1, b2, b3, aK + np*(16*AH*2) + ks*32);
                mma_f16(sacc[2*np    ], qa0, qa1, qa2, qa3, b0, b1);
                mma_f16(sacc[2*np + 1], qa0, qa1, qa2, qa3, b2, b3);
            }
        }

        // ---- online softmax (rows wq+gid, wq+gid+8) ----
        float mt0 = -1e30f, mt1 = -1e30f;
#pragma unroll
        for (int nf = 0; nf < 8; nf++) {
            mt0 = fmaxf(mt0, fmaxf(sacc[nf][0], sacc[nf][1]));
            mt1 = fmaxf(mt1, fmaxf(sacc[nf][2], sacc[nf][3]));
        }
        mt0 = fmaxf(mt0, __shfl_xor_sync(0xffffffffu, mt0, 1));
        mt0 = fmaxf(mt0, __shfl_xor_sync(0xffffffffu, mt0, 2));
        mt1 = fmaxf(mt1, __shfl_xor_sync(0xffffffffu, mt1, 1));
        mt1 = fmaxf(mt1, __shfl_xor_sync(0xffffffffu, mt1, 2));
        const float mn0 = fmaxf(m0, mt0);
        const float mn1 = fmaxf(m1, mt1);

        float rs0 = 0.0f, rs1 = 0.0f;
#pragma unroll
        for (int nf = 0; nf < 8; nf++) {
            const float p00 = __expf(sacc[nf][0] - mn0);
            const float p01 = __expf(sacc[nf][1] - mn0);
            const float p10 = __expf(sacc[nf][2] - mn1);
            const float p11 = __expf(sacc[nf][3] - mn1);
            rs0 += p00 + p01;
            rs1 += p10 + p11;
            const int c = nf*8 + 2*tg;
            *(__half2*)&Ps[(wq+gid  )*AH + c] = __floats2half2_rn(p00, p01);
            *(__half2*)&Ps[(wq+gid+8)*AH + c] = __floats2half2_rn(p10, p11);
        }
        rs0 += __shfl_xor_sync(0xffffffffu, rs0, 1);
        rs0 += __shfl_xor_sync(0xffffffffu, rs0, 2);
        rs1 += __shfl_xor_sync(0xffffffffu, rs1, 1);
        rs1 += __shfl_xor_sync(0xffffffffu, rs1, 2);

        const float al0 = __expf(m0 - mn0);
        const float al1 = __expf(m1 - mn1);
        l0 = l0 * al0 + rs0;  m0 = mn0;
        l1 = l1 * al1 + rs1;  m1 = mn1;
#pragma unroll
        for (int nf = 0; nf < 8; nf++) {
            oacc[nf][0] *= al0; oacc[nf][1] *= al0;
            oacc[nf][2] *= al1; oacc[nf][3] *= al1;
        }
        __syncwarp();   // P visible to this warp's ldmatrix

        // ---- O += P V ----
#pragma unroll
        for (int ks = 0; ks < 4; ks++) {
            uint32_t pa0, pa1, pa2, pa3;
            LDSM_X4(pa0, pa1, pa2, pa3, aP + ks*32);
#pragma unroll
            for (int np = 0; np < 4; np++) {
                uint32_t v0, v1, v2, v3;
                LDSM_X4_T(v0, v1, v2, v3, aV + ks*(16*AH*2) + np*32);
                mma_f16(oacc[2*np    ], pa0, pa1, pa2, pa3, v0, v1);
                mma_f16(oacc[2*np + 1], pa0, pa1, pa2, pa3, v2, v3);
            }
        }
    }

    // ---- epilogue -> half [b, n, h, d] ----
    const int b_ = bh >> 4, h = bh & 15;
    const float inv0 = 1.0f / l0, inv1 = 1.0f / l1;
    const int r0 = q0 + wq + gid, r1 = r0 + 8;
#pragma unroll
    for (int nf = 0; nf < 8; nf++) {
        const int d = nf*8 + 2*tg;
        *(__half2*)&Og[(((size_t)b_*SEQ + r0)*NHEAD + h)*HD + d] =
            __floats2half2_rn(oacc[nf][0]*inv0, oacc[nf][1]*inv0);
        *(__half2*)&Og[(((size_t)b_*SEQ + r1)*NHEAD + h)*HD + d] =
            __floats2half2_rn(oacc[nf][2]*inv1, oacc[nf][3]*inv1);
    }
}

// ---------------------------------------------------------------------------
extern "C" void kernel_launch(void* const* d_in, const int* in_sizes, int n_in,
                              void* d_out, int out_size)
{
    const float* x  = (const float*)d_in[0];
    const float* Wq = (const float*)d_in[1];
    const float* bq = (const float*)d_in[2];
    const float* Wk = (const float*)d_in[3];
    const float* bk = (const float*)d_in[4];
    const float* Wv = (const float*)d_in[5];
    const float* bv = (const float*)d_in[6];
    const float* Wo = (const float*)d_in[7];
    const float* bo = (const float*)d_in[8];
    float* out = (float*)d_out;

    __half *Xh, *Wqh, *Wkh, *Wvh, *Woh, *Qh, *Kh, *Vh, *Ah;
    cudaGetSymbolAddress((void**)&Xh,  g_Xh);
    cudaGetSymbolAddress((void**)&Wqh, g_Wqh);
    cudaGetSymbolAddress((void**)&Wkh, g_Wkh);
    cudaGetSymbolAddress((void**)&Wvh, g_Wvh);
    cudaGetSymbolAddress((void**)&Woh, g_Woh);
    cudaGetSymbolAddress((void**)&Qh,  g_Qh);
    cudaGetSymbolAddress((void**)&Kh,  g_Kh);
    cudaGetSymbolAddress((void**)&Vh,  g_Vh);
    cudaGetSymbolAddress((void**)&Ah,  g_Ah);

    cudaFuncSetAttribute(gemm_h_kernel, cudaFuncAttributeMaxDynamicSharedMemorySize,
                         GSMB);
    cudaFuncSetAttribute(attn_h_kernel, cudaFuncAttributeMaxDynamicSharedMemorySize,
                         ATT_BYTES);

    const int NX4 = MROWS*FEATS/4;      // 2097152
    const int NW4 = FEATS*FEATS/4;      // 262144
    cvt_kernel<<<(NX4+255)/256, 256>>>((const float4*)x,  (uint2*)Xh,  NX4);
    cvt_kernel<<<(NW4+255)/256, 256>>>((const float4*)Wq, (uint2*)Wqh, NW4);
    cvt_kernel<<<(NW4+255)/256, 256>>>((const float4*)Wk, (uint2*)Wkh, NW4);
    cvt_kernel<<<(NW4+255)/256, 256>>>((const float4*)Wv, (uint2*)Wvh, NW4);
    cvt_kernel<<<(NW4+255)/256, 256>>>((const float4*)Wo, (uint2*)Woh, NW4);

    dim3 ggrid(MROWS/128, FEATS/128);   // (64, 8)
    gemm_h_kernel<<<ggrid, 256, GSMB>>>(Xh, Wqh, bq, nullptr, Qh, 2);
    gemm_h_kernel<<<ggrid, 256, GSMB>>>(Xh, Wkh, bk, nullptr, Kh, 1);
    gemm_h_kernel<<<ggrid, 256, GSMB>>>(Xh, Wvh, bv, nullptr, Vh, 1);

    dim3 agrid(SEQ/128, BATCH*NHEAD);   // (16, 64)
    attn_h_kernel<<<agrid, 256, ATT_BYTES>>>(Qh, Kh, Vh, Ah);

    gemm_h_kernel<<<ggrid, 256, GSMB>>>(Ah, Woh, bo, out, nullptr, 0);
}

// round 17
// speedup vs baseline: 7.2521x; 1.0182x over previous
#include <cuda_runtime.h>
#include <cuda_fp16.h>
#include <cstdint>
#include <math.h>

#define BATCH 4
#define SEQ   2048
#define FEATS 1024
#define NHEAD 16
#define HD    64
#define MROWS (BATCH*SEQ)

// ---------------- scratch (static device globals; no allocations) ----------
__device__ __half g_Xh[MROWS*FEATS];
__device__ __half g_Wqh[FEATS*FEATS];
__device__ __half g_Wkh[FEATS*FEATS];
__device__ __half g_Wvh[FEATS*FEATS];
__device__ __half g_Woh[FEATS*FEATS];
__device__ __half g_Qh[BATCH*NHEAD*SEQ*HD];   // [b,h,n,d], pre-scaled log2e/32
__device__ __half g_Kh[BATCH*NHEAD*SEQ*HD];
__device__ __half g_Vh[BATCH*NHEAD*SEQ*HD];
__device__ __half g_Ah[MROWS*FEATS];          // attention out, [b,n,h,d]

// ======================= portable PTX helpers ==============================
__device__ __forceinline__ uint32_t smem_u32(const void* p) {
    uint32_t a;
    asm("{ .reg .u64 t; cvta.to.shared.u64 t, %1; cvt.u32.u64 %0, t; }"
        : "=r"(a) : "l"(p));
    return a;
}
#define CP_ASYNC16(saddr, gptr) \
    asm volatile("cp.async.cg.shared.global [%0], [%1], 16;" \
        :: "r"((uint32_t)(saddr)), "l"(gptr))
#define CP_COMMIT() asm volatile("cp.async.commit_group;" ::: "memory")
#define CP_WAIT(n)  asm volatile("cp.async.wait_group %0;" :: "n"(n) : "memory")

#define LDSM_X4(r0, r1, r2, r3, addr) \
    asm volatile("ldmatrix.sync.aligned.m8n8.x4.shared.b16 {%0,%1,%2,%3}, [%4];" \
        : "=r"(r0), "=r"(r1), "=r"(r2), "=r"(r3) : "r"(addr))
#define LDSM_X4_T(r0, r1, r2, r3, addr) \
    asm volatile("ldmatrix.sync.aligned.m8n8.x4.trans.shared.b16 {%0,%1,%2,%3}, [%4];" \
        : "=r"(r0), "=r"(r1), "=r"(r2), "=r"(r3) : "r"(addr))

__device__ __forceinline__ uint32_t packh2(float x, float y) {
    __half2 h = __floats2half2_rn(x, y);
    return *(uint32_t*)&h;
}
__device__ __forceinline__ float ex2f(float x) {
    float r;
    asm("ex2.approx.f32 %0, %1;" : "=f"(r) : "f"(x));
    return r;
}
__device__ __forceinline__ void mma_f16(float c[4], uint32_t a0, uint32_t a1,
                                        uint32_t a2, uint32_t a3,
                                        uint32_t b0, uint32_t b1) {
    asm volatile(
        "mma.sync.aligned.m16n8k16.row.col.f32.f16.f16.f32 "
        "{%0,%1,%2,%3}, {%4,%5,%6,%7}, {%8,%9}, {%0,%1,%2,%3};"
        : "+f"(c[0]), "+f"(c[1]), "+f"(c[2]), "+f"(c[3])
        : "r"(a0), "r"(a1), "r"(a2), "r"(a3), "r"(b0), "r"(b1));
}

// ---------------------------------------------------------------------------
// fp32 -> fp16 convert (vectorized)
// ---------------------------------------------------------------------------
__global__ __launch_bounds__(256) void cvt_kernel(const float4* __restrict__ src,
                                                  uint2* __restrict__ dst, int n4)
{
    int i = blockIdx.x*256 + threadIdx.x;
    if (i < n4) {
        float4 v = src[i];
        dst[i] = make_uint2(packh2(v.x, v.y), packh2(v.z, v.w));
    }
}

// ---------------------------------------------------------------------------
// fp16-in GEMM, 3-stage cp.async pipeline, single barrier per chunk.
// C[m, col] = sum_k X[m,k] * W[col,k] + bias[col]
// layout: 0 -> float out [m,f]; 1 -> half out [b,h,n,d]; 2 -> same * log2e/32.
// ---------------------------------------------------------------------------
#define SH 72
#define GBUFB (128*SH*2)          // 18432 bytes per tile buffer
#define GSMB  (6*GBUFB)           // 110592
#define NCHUNK (FEATS/64)         // 16

__device__ __forceinline__ void stage_h(
    const __half* __restrict__ X, const __half* __restrict__ W,
    uint32_t sA, uint32_t sB, int mrow0, int ncol0, int k0, int tid)
{
    const int r0 = tid >> 2, c = tid & 3;
#pragma unroll
    for (int rr = 0; rr < 2; rr++) {
        const int r = r0 + rr*64;
#pragma unroll
        for (int ff = 0; ff < 2; ff++) {
            const int c16 = c + ff*4;
            CP_ASYNC16(sA + (uint32_t)(r*SH + c16*8)*2,
                       X + (size_t)(mrow0 + r)*FEATS + k0 + c16*8);
            CP_ASYNC16(sB + (uint32_t)(r*SH + c16*8)*2,
                       W + (size_t)(ncol0 + r)*FEATS + k0 + c16*8);
        }
    }
}

__global__ __launch_bounds__(256, 2) void gemm_h_kernel(
    const __half* __restrict__ X, const __half* __restrict__ W,
    const float* __restrict__ bias, float* __restrict__ Cf,
    __half* __restrict__ Ch, int layout)
{
    extern __shared__ __align__(16) __half smh[];
    const uint32_t smem_base = smem_u32(smh);

    const int tid  = threadIdx.x;
    const int wid  = tid >> 5, lane = tid & 31;
    const int gid  = lane >> 2, tg = lane & 3;
    const int l7   = lane & 7;
    const int wm0  = (wid & 1) * 64;
    const int wn0  = (wid >> 1) * 32;
    const int mrow0 = blockIdx.x * 128;
    const int ncol0 = blockIdx.y * 128;

    const uint32_t sA0 = smem_base;                 // 3 A buffers
    const uint32_t sB0 = smem_base + 3*GBUFB;       // 3 B buffers

    const uint32_t aA0 = smem_u32(&smh[(wm0 + l7 + (lane & 8))*SH + ((lane >> 4) << 3)]);
    const uint32_t aB0 = smem_u32(&smh[3*128*SH + (wn0 + l7 + ((lane >> 1) & 8))*SH + (lane & 8)]);

    float acc[4][4][4];
#pragma unroll
    for (int i = 0; i < 4; i++)
#pragma unroll
        for (int j = 0; j < 4; j++)
#pragma unroll
            for (int q = 0; q < 4; q++) acc[i][j][q] = 0.0f;

    stage_h(X, W, sA0, sB0, mrow0, ncol0, 0, tid);
    CP_COMMIT();
    stage_h(X, W, sA0 + GBUFB, sB0 + GBUFB, mrow0, ncol0, 64, tid);
    CP_COMMIT();

    int buf = 0, sbuf = 2;
    for (int ck = 0; ck < NCHUNK; ck++) {
        if (ck == NCHUNK - 1) { CP_WAIT(0); } else { CP_WAIT(1); }
        __syncthreads();
        if (ck + 2 < NCHUNK) {
            stage_h(X, W, sA0 + sbuf*GBUFB, sB0 + sbuf*GBUFB,
                    mrow0, ncol0, (ck+2)*64, tid);
            CP_COMMIT();
        }

        const uint32_t aA = aA0 + buf*GBUFB;
        const uint32_t aB = aB0 + buf*GBUFB;
#pragma unroll
        for (int ks = 0; ks < 4; ks++) {
            uint32_t a[4][4];
#pragma unroll
            for (int mf = 0; mf < 4; mf++)
                LDSM_X4(a[mf][0], a[mf][1], a[mf][2], a[mf][3],
                        aA + mf*(16*SH*2) + ks*32);
#pragma unroll
            for (int nh = 0; nh < 2; nh++) {
                uint32_t b0, b1, b2, b3;
                LDSM_X4(b0, b1, b2, b3, aB + nh*(16*SH*2) + ks*32);
#pragma unroll
                for (int mf = 0; mf < 4; mf++) {
                    mma_f16(acc[mf][2*nh    ], a[mf][0], a[mf][1], a[mf][2], a[mf][3], b0, b1);
                    mma_f16(acc[mf][2*nh + 1], a[mf][0], a[mf][1], a[mf][2], a[mf][3], b2, b3);
                }
            }
        }
        buf = (buf == 2) ? 0 : buf + 1;
        sbuf = (sbuf == 2) ? 0 : sbuf + 1;
    }

    const float osc = (layout == 2) ? (1.4426950408889634f/32.0f) : 1.0f;
#pragma unroll
    for (int nf = 0; nf < 4; nf++) {
        const int col = ncol0 + wn0 + nf*8 + 2*tg;
        const float bv0 = bias[col], bv1 = bias[col + 1];
        const int h = col >> 6, d = col & 63;
#pragma unroll
        for (int mf = 0; mf < 4; mf++) {
#pragma unroll
            for (int half = 0; half < 2; half++) {
                const int m = mrow0 + wm0 + mf*16 + gid + half*8;
                const float v0 = (acc[mf][nf][half*2 + 0] + bv0) * osc;
                const float v1 = (acc[mf][nf][half*2 + 1] + bv1) * osc;
                if (layout) {
                    const int b_ = m >> 11, ns = m & (SEQ - 1);
                    *(__half2*)&Ch[(((size_t)(b_*NHEAD + h))*SEQ + ns)*HD + d] =
                        __floats2half2_rn(v0, v1);
                } else {
                    *(float2*)&Cf[(size_t)m*FEATS + col] = make_float2(v0, v1);
                }
            }
        }
    }
}

// ---------------------------------------------------------------------------
// Flash attention, 3-stage K/V pipeline, single barrier per tile, exp2 softmax.
// Smem rows (stride AH=72 halfs): Q:0-127, K0..K2:128-319, V0..V2:320-511,
// P:512-639.  92160 B, 2 CTAs/SM.  Q arrives pre-scaled by log2e/32.
// ---------------------------------------------------------------------------
#define AH 72
#define KVBUFB (64*AH*2)            // 9216 bytes per K/V buffer
#define ATT_BYTES (640*AH*2)        // 92160
#define NKT (SEQ/64)                // 32

__global__ __launch_bounds__(256, 2) void attn_h_kernel(
    const __half* __restrict__ Qg, const __half* __restrict__ Kg,
    const __half* __restrict__ Vg, __half* __restrict__ Og)
{
    extern __shared__ __align__(16) __half smh[];
    __half* Qs = smh;                       // [128][AH]
    __half* Ps = smh + 512*AH;              // [128][AH]
    const uint32_t sQ  = smem_u32(smh);
    const uint32_t sK0 = sQ + 128*AH*2;
    const uint32_t sV0 = sQ + 320*AH*2;

    const int tid  = threadIdx.x;
    const int wid  = tid >> 5, lane = tid & 31;
    const int gid  = lane >> 2, tg = lane & 3;
    const int wq   = wid * 16;
    const int l7   = lane & 7;

    const int bh = blockIdx.y;
    const int q0 = blockIdx.x * 128;
    const __half* Qb = Qg + ((size_t)bh * SEQ + q0) * HD;
    const __half* Kb = Kg + (size_t)bh * SEQ * HD;
    const __half* Vb = Vg + (size_t)bh * SEQ * HD;

    const uint32_t aQ  = smem_u32(&Qs[(wq + l7 + (lane & 8))*AH + ((lane >> 4) << 3)]);
    const uint32_t aP  = smem_u32(&Ps[(wq + l7 + (lane & 8))*AH + ((lane >> 4) << 3)]);
    const uint32_t aK0 = sK0 + ((l7 + ((lane >> 1) & 8))*AH + (lane & 8))*2;
    const uint32_t aV0 = sV0 + ((l7 + (lane & 8))*AH + ((lane >> 1) & 8))*2;

    // ---- prologue: Q + KV tile0 (group 0), KV tile1 (group 1) ----
    {
        const int r = tid >> 1, c = tid & 1;
#pragma unroll
        for (int j = 0; j < 4; j++) {
            const int c16 = c + j*2;
            CP_ASYNC16(sQ + (uint32_t)(r*AH + c16*8)*2, Qb + r*HD + c16*8);
        }
    }
    {
        const int r = tid >> 2, c = tid & 3;
#pragma unroll
        for (int j = 0; j < 2; j++) {
            const int c16 = c + j*4;
            CP_ASYNC16(sK0 + (uint32_t)(r*AH + c16*8)*2, Kb + r*HD + c16*8);
            CP_ASYNC16(sV0 + (uint32_t)(r*AH + c16*8)*2, Vb + r*HD + c16*8);
        }
        CP_COMMIT();
#pragma unroll
        for (int j = 0; j < 2; j++) {
            const int c16 = c + j*4;
            CP_ASYNC16(sK0 + KVBUFB + (uint32_t)(r*AH + c16*8)*2, Kb + 64*HD + r*HD + c16*8);
            CP_ASYNC16(sV0 + KVBUFB + (uint32_t)(r*AH + c16*8)*2, Vb + 64*HD + r*HD + c16*8);
        }
        CP_COMMIT();
    }

    float m0 = -1e30f, m1 = -1e30f, l0 = 0.0f, l1 = 0.0f;
    float oacc[8][4];
#pragma unroll
    for (int nf = 0; nf < 8; nf++)
#pragma unroll
        for (int q = 0; q < 4; q++) oacc[nf][q] = 0.0f;

    int buf = 0, sbuf = 2;
    for (int kt = 0; kt < NKT; kt++) {
        if (kt == NKT - 1) { CP_WAIT(0); } else { CP_WAIT(1); }
        __syncthreads();

        if (kt + 2 < NKT) {
            const __half* Kt = Kb + (size_t)(kt+2) * 64 * HD;
            const __half* Vt = Vb + (size_t)(kt+2) * 64 * HD;
            const int r = tid >> 2, c = tid & 3;
#pragma unroll
            for (int j = 0; j < 2; j++) {
                const int c16 = c + j*4;
                CP_ASYNC16(sK0 + sbuf*KVBUFB + (uint32_t)(r*AH + c16*8)*2, Kt + r*HD + c16*8);
                CP_ASYNC16(sV0 + sbuf*KVBUFB + (uint32_t)(r*AH + c16*8)*2, Vt + r*HD + c16*8);
            }
            CP_COMMIT();
        }

        const uint32_t aK = aK0 + buf*KVBUFB;
        const uint32_t aV = aV0 + buf*KVBUFB;

        // ---- S' = (Q*log2e/32) K^T ----
        float sacc[8][4];
#pragma unroll
        for (int nf = 0; nf < 8; nf++)
#pragma unroll
            for (int q = 0; q < 4; q++) sacc[nf][q] = 0.0f;

#pragma unroll
        for (int ks = 0; ks < 4; ks++) {
            uint32_t qa0, qa1, qa2, qa3;
            LDSM_X4(qa0, qa1, qa2, qa3, aQ + ks*32);
#pragma unroll
            for (int np = 0; np < 4; np++) {
                uint32_t b0, b1, b2, b3;
                LDSM_X4(b0, b1, b2, b3, aK + np*(16*AH*2) + ks*32);
                mma_f16(sacc[2*np    ], qa0, qa1, qa2, qa3, b0, b1);
                mma_f16(sacc[2*np + 1], qa0, qa1, qa2, qa3, b2, b3);
            }
        }

        // ---- online softmax in exp2 domain ----
        float mt0 = -1e30f, mt1 = -1e30f;
#pragma unroll
        for (int nf = 0; nf < 8; nf++) {
            mt0 = fmaxf(mt0, fmaxf(sacc[nf][0], sacc[nf][1]));
            mt1 = fmaxf(mt1, fmaxf(sacc[nf][2], sacc[nf][3]));
        }
        mt0 = fmaxf(mt0, __shfl_xor_sync(0xffffffffu, mt0, 1));
        mt0 = fmaxf(mt0, __shfl_xor_sync(0xffffffffu, mt0, 2));
        mt1 = fmaxf(mt1, __shfl_xor_sync(0xffffffffu, mt1, 1));
        mt1 = fmaxf(mt1, __shfl_xor_sync(0xffffffffu, mt1, 2));
        const float mn0 = fmaxf(m0, mt0);
        const float mn1 = fmaxf(m1, mt1);

        float rs0 = 0.0f, rs1 = 0.0f;
#pragma unroll
        for (int nf = 0; nf < 8; nf++) {
            const float p00 = ex2f(sacc[nf][0] - mn0);
            const float p01 = ex2f(sacc[nf][1] - mn0);
            const float p10 = ex2f(sacc[nf][2] - mn1);
            const float p11 = ex2f(sacc[nf][3] - mn1);
            rs0 += p00 + p01;
            rs1 += p10 + p11;
            const int c = nf*8 + 2*tg;
            *(__half2*)&Ps[(wq+gid  )*AH + c] = __floats2half2_rn(p00, p01);
            *(__half2*)&Ps[(wq+gid+8)*AH + c] = __floats2half2_rn(p10, p11);
        }
        rs0 += __shfl_xor_sync(0xffffffffu, rs0, 1);
        rs0 += __shfl_xor_sync(0xffffffffu, rs0, 2);
        rs1 += __shfl_xor_sync(0xffffffffu, rs1, 1);
        rs1 += __shfl_xor_sync(0xffffffffu, rs1, 2);

        const float al0 = ex2f(m0 - mn0);
        const float al1 = ex2f(m1 - mn1);
        l0 = l0 * al0 + rs0;  m0 = mn0;
        l1 = l1 * al1 + rs1;  m1 = mn1;
#pragma unroll
        for (int nf = 0; nf < 8; nf++) {
            oacc[nf][0] *= al0; oacc[nf][1] *= al0;
            oacc[nf][2] *= al1; oacc[nf][3] *= al1;
        }
        __syncwarp();   // P visible to this warp's ldmatrix

        // ---- O += P V ----
#pragma unroll
        for (int ks = 0; ks < 4; ks++) {
            uint32_t pa0, pa1, pa2, pa3;
            LDSM_X4(pa0, pa1, pa2, pa3, aP + ks*32);
#pragma unroll
            for (int np = 0; np < 4; np++) {
                uint32_t v0, v1, v2, v3;
                LDSM_X4_T(v0, v1, v2, v3, aV + ks*(16*AH*2) + np*32);
                mma_f16(oacc[2*np    ], pa0, pa1, pa2, pa3, v0, v1);
                mma_f16(oacc[2*np + 1], pa0, pa1, pa2, pa3, v2, v3);
            }
        }
        buf = (buf == 2) ? 0 : buf + 1;
        sbuf = (sbuf == 2) ? 0 : sbuf + 1;
    }

    // ---- epilogue -> half [b, n, h, d] ----
    const int b_ = bh >> 4, h = bh & 15;
    const float inv0 = 1.0f / l0, inv1 = 1.0f / l1;
    const int r0 = q0 + wq + gid, r1 = r0 + 8;
#pragma unroll
    for (int nf = 0; nf < 8; nf++) {
        const int d = nf*8 + 2*tg;
        *(__half2*)&Og[(((size_t)b_*SEQ + r0)*NHEAD + h)*HD + d] =
            __floats2half2_rn(oacc[nf][0]*inv0, oacc[nf][1]*inv0);
        *(__half2*)&Og[(((size_t)b_*SEQ + r1)*NHEAD + h)*HD + d] =
            __floats2half2_rn(oacc[nf][2]*inv1, oacc[nf][3]*inv1);
    }
}

// ---------------------------------------------------------------------------
extern "C" void kernel_launch(void* const* d_in, const int* in_sizes, int n_in,
                              void* d_out, int out_size)
{
    const float* x  = (const float*)d_in[0];
    const float* Wq = (const float*)d_in[1];
    const float* bq = (const float*)d_in[2];
    const float* Wk = (const float*)d_in[3];
    const float* bk = (const float*)d_in[4];
    const float* Wv = (const float*)d_in[5];
    const float* bv = (const float*)d_in[6];
    const float* Wo = (const float*)d_in[7];
    const float* bo = (const float*)d_in[8];
    float* out = (float*)d_out;

    __half *Xh, *Wqh, *Wkh, *Wvh, *Woh, *Qh, *Kh, *Vh, *Ah;
    cudaGetSymbolAddress((void**)&Xh,  g_Xh);
    cudaGetSymbolAddress((void**)&Wqh, g_Wqh);
    cudaGetSymbolAddress((void**)&Wkh, g_Wkh);
    cudaGetSymbolAddress((void**)&Wvh, g_Wvh);
    cudaGetSymbolAddress((void**)&Woh, g_Woh);
    cudaGetSymbolAddress((void**)&Qh,  g_Qh);
    cudaGetSymbolAddress((void**)&Kh,  g_Kh);
    cudaGetSymbolAddress((void**)&Vh,  g_Vh);
    cudaGetSymbolAddress((void**)&Ah,  g_Ah);

    cudaFuncSetAttribute(gemm_h_kernel, cudaFuncAttributeMaxDynamicSharedMemorySize,
                         GSMB);
    cudaFuncSetAttribute(attn_h_kernel, cudaFuncAttributeMaxDynamicSharedMemorySize,
                         ATT_BYTES);

    const int NX4 = MROWS*FEATS/4;      // 2097152
    const int NW4 = FEATS*FEATS/4;      // 262144
    cvt_kernel<<<(NX4+255)/256, 256>>>((const float4*)x,  (uint2*)Xh,  NX4);
    cvt_kernel<<<(NW4+255)/256, 256>>>((const float4*)Wq, (uint2*)Wqh, NW4);
    cvt_kernel<<<(NW4+255)/256, 256>>>((const float4*)Wk, (uint2*)Wkh, NW4);
    cvt_kernel<<<(NW4+255)/256, 256>>>((const float4*)Wv, (uint2*)Wvh, NW4);
    cvt_kernel<<<(NW4+255)/256, 256>>>((const float4*)Wo, (uint2*)Woh, NW4);

    dim3 ggrid(MROWS/128, FEATS/128);   // (64, 8)
    gemm_h_kernel<<<ggrid, 256, GSMB>>>(Xh, Wqh, bq, nullptr, Qh, 2);
    gemm_h_kernel<<<ggrid, 256, GSMB>>>(Xh, Wkh, bk, nullptr, Kh, 1);
    gemm_h_kernel<<<ggrid, 256, GSMB>>>(Xh, Wvh, bv, nullptr, Vh, 1);

    dim3 agrid(SEQ/128, BATCH*NHEAD);   // (16, 64)
    attn_h_kernel<<<agrid, 256, ATT_BYTES>>>(Qh, Kh, Vh, Ah);

    gemm_h_kernel<<<ggrid, 256, GSMB>>>(Ah, Woh, bo, out, nullptr, 0);
}